// round 2
// baseline (speedup 1.0000x reference)
#include <cuda_runtime.h>
#include <cstdint>

// Problem constants
#define B_  2
#define S_  2048
#define D_  1024
#define H_  16
#define DK_ 64
#define M_  (B_ * S_)   // 4096 rows for projection GEMMs

// ---------------------------------------------------------------------------
// Scratch (allocation-free rule: __device__ globals)
// ---------------------------------------------------------------------------
__device__ float g_Q[M_ * D_];   // projected Q, [B,S,D] layout
__device__ float g_K[M_ * D_];   // projected K
__device__ float g_V[M_ * D_];   // projected V
__device__ float g_C[M_ * D_];   // attention context (pre output proj), [B,S,D]

// ---------------------------------------------------------------------------
// GEMM with bias: Y[M,N] = X[M,K] @ W[N,K]^T + bias[N]
// Tiles: 128x128x32, 256 threads, 8x8 micro-tile per thread.
// ---------------------------------------------------------------------------
#define GBM 128
#define GBN 128
#define GBK 32

__global__ __launch_bounds__(256) void gemm_bias_kernel(
    const float* __restrict__ X, const float* __restrict__ W,
    const float* __restrict__ bias, float* __restrict__ Y,
    int M, int N, int K)
{
    __shared__ float As[GBK][GBM + 4];
    __shared__ float Bs[GBK][GBN + 4];

    const int tid = threadIdx.x;
    const int tx = tid & 15;       // 0..15
    const int ty = tid >> 4;       // 0..15
    const int m0 = blockIdx.y * GBM;
    const int n0 = blockIdx.x * GBN;

    float acc[8][8];
#pragma unroll
    for (int i = 0; i < 8; i++)
#pragma unroll
        for (int j = 0; j < 8; j++) acc[i][j] = 0.0f;

    const int lrow = tid >> 3;   // 0..31 base row among 128 (x4 iters)
    const int lkq  = tid & 7;    // float4 index in k

    for (int k0 = 0; k0 < K; k0 += GBK) {
        // Issue all 8 global loads first (MLP), then scatter to smem.
        float4 av[4], bv[4];
#pragma unroll
        for (int i = 0; i < 4; i++) {
            int row = lrow + i * 32;
            av[i] = *(const float4*)&X[(size_t)(m0 + row) * K + k0 + lkq * 4];
            bv[i] = *(const float4*)&W[(size_t)(n0 + row) * K + k0 + lkq * 4];
        }
#pragma unroll
        for (int i = 0; i < 4; i++) {
            int row = lrow + i * 32;
            As[lkq * 4 + 0][row] = av[i].x;
            As[lkq * 4 + 1][row] = av[i].y;
            As[lkq * 4 + 2][row] = av[i].z;
            As[lkq * 4 + 3][row] = av[i].w;
            Bs[lkq * 4 + 0][row] = bv[i].x;
            Bs[lkq * 4 + 1][row] = bv[i].y;
            Bs[lkq * 4 + 2][row] = bv[i].z;
            Bs[lkq * 4 + 3][row] = bv[i].w;
        }
        __syncthreads();

#pragma unroll
        for (int k = 0; k < GBK; k++) {
            float a[8], b[8];
            float4 a0 = *(const float4*)&As[k][ty * 8];
            float4 a1 = *(const float4*)&As[k][ty * 8 + 4];
            float4 b0 = *(const float4*)&Bs[k][tx * 8];
            float4 b1 = *(const float4*)&Bs[k][tx * 8 + 4];
            a[0] = a0.x; a[1] = a0.y; a[2] = a0.z; a[3] = a0.w;
            a[4] = a1.x; a[5] = a1.y; a[6] = a1.z; a[7] = a1.w;
            b[0] = b0.x; b[1] = b0.y; b[2] = b0.z; b[3] = b0.w;
            b[4] = b1.x; b[5] = b1.y; b[6] = b1.z; b[7] = b1.w;
#pragma unroll
            for (int i = 0; i < 8; i++)
#pragma unroll
                for (int j = 0; j < 8; j++)
                    acc[i][j] += a[i] * b[j];
        }
        __syncthreads();
    }

    // Epilogue with bias
#pragma unroll
    for (int i = 0; i < 8; i++) {
        int m = m0 + ty * 8 + i;
#pragma unroll
        for (int j = 0; j < 8; j += 4) {
            int n = n0 + tx * 8 + j;
            float4 o;
            o.x = acc[i][j + 0] + bias[n + 0];
            o.y = acc[i][j + 1] + bias[n + 1];
            o.z = acc[i][j + 2] + bias[n + 2];
            o.w = acc[i][j + 3] + bias[n + 3];
            *(float4*)&Y[(size_t)m * N + n] = o;
        }
    }
}

// ---------------------------------------------------------------------------
// Fused attention (flash-style online softmax).
// Grid: (S/64, B*H). Block: 256 threads.
// ---------------------------------------------------------------------------
#define TQ 64
#define TK 64
#define LDP 68

#define ATTN_SMEM_FLOATS (4 * TQ * LDP + 3 * TQ)
#define ATTN_SMEM_BYTES  (ATTN_SMEM_FLOATS * 4)

__global__ __launch_bounds__(256) void attn_kernel(
    const float* __restrict__ Q, const float* __restrict__ K,
    const float* __restrict__ V, const int* __restrict__ mask,
    float* __restrict__ C)
{
    extern __shared__ float smem[];
    float (*sQ)[LDP] = (float (*)[LDP])(smem);
    float (*sK)[LDP] = (float (*)[LDP])(smem + 1 * TQ * LDP);
    float (*sV)[LDP] = (float (*)[LDP])(smem + 2 * TQ * LDP);
    float (*sS)[LDP] = (float (*)[LDP])(smem + 3 * TQ * LDP);
    float* sM    = smem + 4 * TQ * LDP;
    float* sL    = sM + TQ;
    float* sCorr = sL + TQ;

    const int tid = threadIdx.x;
    const int tx = tid & 15;    // 0..15 (4 cols each)
    const int ty = tid >> 4;    // 0..15 (4 rows each)
    const int bh = blockIdx.y;
    const int b  = bh / H_;
    const int h  = bh % H_;
    const int q0 = blockIdx.x * TQ;

    const float* Qb = Q + (size_t)b * S_ * D_ + (size_t)h * DK_;
    const float* Kb = K + (size_t)b * S_ * D_ + (size_t)h * DK_;
    const float* Vb = V + (size_t)b * S_ * D_ + (size_t)h * DK_;
    const int*   Mb = mask + (size_t)b * S_ * S_;

    // Load Q tile
#pragma unroll
    for (int i = 0; i < 4; i++) {
        int idx = tid + i * 256;
        int r  = idx >> 4;
        int c4 = idx & 15;
        *(float4*)&sQ[r][c4 * 4] =
            *(const float4*)&Qb[(size_t)(q0 + r) * D_ + c4 * 4];
    }
    if (tid < TQ) { sM[tid] = -1e30f; sL[tid] = 0.0f; }

    float o[4][4];
#pragma unroll
    for (int i = 0; i < 4; i++)
#pragma unroll
        for (int j = 0; j < 4; j++) o[i][j] = 0.0f;

    __syncthreads();

    for (int k0 = 0; k0 < S_; k0 += TK) {
        // Load K and V tiles
#pragma unroll
        for (int i = 0; i < 4; i++) {
            int idx = tid + i * 256;
            int r  = idx >> 4;
            int c4 = idx & 15;
            *(float4*)&sK[r][c4 * 4] =
                *(const float4*)&Kb[(size_t)(k0 + r) * D_ + c4 * 4];
            *(float4*)&sV[r][c4 * 4] =
                *(const float4*)&Vb[(size_t)(k0 + r) * D_ + c4 * 4];
        }
        __syncthreads();

        // S = (Q @ K^T) / 8, masked; 4x4 per thread
        float s[4][4];
#pragma unroll
        for (int i = 0; i < 4; i++)
#pragma unroll
            for (int j = 0; j < 4; j++) s[i][j] = 0.0f;

#pragma unroll
        for (int d = 0; d < DK_; d++) {
            float a[4], bb[4];
#pragma unroll
            for (int i = 0; i < 4; i++) a[i]  = sQ[ty * 4 + i][d];
#pragma unroll
            for (int j = 0; j < 4; j++) bb[j] = sK[tx * 4 + j][d];
#pragma unroll
            for (int i = 0; i < 4; i++)
#pragma unroll
                for (int j = 0; j < 4; j++)
                    s[i][j] += a[i] * bb[j];
        }

#pragma unroll
        for (int i = 0; i < 4; i++) {
            int qr = q0 + ty * 4 + i;
            int4 mrow = *(const int4*)&Mb[(size_t)qr * S_ + k0 + tx * 4];
            float v0 = s[i][0] * 0.125f;
            float v1 = s[i][1] * 0.125f;
            float v2 = s[i][2] * 0.125f;
            float v3 = s[i][3] * 0.125f;
            if (mrow.x == 0) v0 = -1e9f;
            if (mrow.y == 0) v1 = -1e9f;
            if (mrow.z == 0) v2 = -1e9f;
            if (mrow.w == 0) v3 = -1e9f;
            sS[ty * 4 + i][tx * 4 + 0] = v0;
            sS[ty * 4 + i][tx * 4 + 1] = v1;
            sS[ty * 4 + i][tx * 4 + 2] = v2;
            sS[ty * 4 + i][tx * 4 + 3] = v3;
        }
        __syncthreads();

        // Online softmax: 4 threads per row (256 threads / 64 rows).
        // Thread group g = tid&3 handles columns [g*16, g*16+16).
        {
            int r = tid >> 2;        // 0..63
            int g = tid & 3;         // 0..3
            float rowmax = -1e30f;
#pragma unroll
            for (int c = 0; c < 16; c++)
                rowmax = fmaxf(rowmax, sS[r][g * 16 + c]);
            // reduce across the 4 threads (they are adjacent lanes)
            rowmax = fmaxf(rowmax, __shfl_xor_sync(0xFFFFFFFF, rowmax, 1));
            rowmax = fmaxf(rowmax, __shfl_xor_sync(0xFFFFFFFF, rowmax, 2));
            float mprev = sM[r];
            float nm = fmaxf(mprev, rowmax);
            float sum = 0.0f;
#pragma unroll
            for (int c = 0; c < 16; c++) {
                float p = __expf(sS[r][g * 16 + c] - nm);
                sS[r][g * 16 + c] = p;
                sum += p;
            }
            sum += __shfl_xor_sync(0xFFFFFFFF, sum, 1);
            sum += __shfl_xor_sync(0xFFFFFFFF, sum, 2);
            if (g == 0) {
                float corr = __expf(mprev - nm);
                sL[r] = sL[r] * corr + sum;
                sM[r] = nm;
                sCorr[r] = corr;
            }
        }
        __syncthreads();

        // Rescale O and accumulate O += P @ V
        float cr[4];
#pragma unroll
        for (int i = 0; i < 4; i++) cr[i] = sCorr[ty * 4 + i];
#pragma unroll
        for (int i = 0; i < 4; i++)
#pragma unroll
            for (int j = 0; j < 4; j++) o[i][j] *= cr[i];

#pragma unroll
        for (int kk = 0; kk < TK; kk++) {
            float p[4], vv[4];
#pragma unroll
            for (int i = 0; i < 4; i++) p[i]  = sS[ty * 4 + i][kk];
#pragma unroll
            for (int j = 0; j < 4; j++) vv[j] = sV[kk][tx * 4 + j];
#pragma unroll
            for (int i = 0; i < 4; i++)
#pragma unroll
                for (int j = 0; j < 4; j++)
                    o[i][j] += p[i] * vv[j];
        }
        __syncthreads();
    }

    // Finalize: divide by row sums, write context in [B,S,D] layout
    float inv[4];
#pragma unroll
    for (int i = 0; i < 4; i++) inv[i] = 1.0f / sL[ty * 4 + i];

    float* Cb = C + (size_t)b * S_ * D_ + (size_t)h * DK_;
#pragma unroll
    for (int i = 0; i < 4; i++) {
        int qr = q0 + ty * 4 + i;
        float4 ov;
        ov.x = o[i][0] * inv[i];
        ov.y = o[i][1] * inv[i];
        ov.z = o[i][2] * inv[i];
        ov.w = o[i][3] * inv[i];
        *(float4*)&Cb[(size_t)qr * D_ + tx * 4] = ov;
    }
}

// ---------------------------------------------------------------------------
// Launch
// ---------------------------------------------------------------------------
extern "C" void kernel_launch(void* const* d_in, const int* in_sizes, int n_in,
                              void* d_out, int out_size)
{
    (void)in_sizes; (void)n_in; (void)out_size;
    const float* q    = (const float*)d_in[0];
    const float* k    = (const float*)d_in[1];
    const float* v    = (const float*)d_in[2];
    const int*   mask = (const int*)d_in[3];
    const float* w_q  = (const float*)d_in[4];
    const float* b_q  = (const float*)d_in[5];
    const float* w_k  = (const float*)d_in[6];
    const float* b_k  = (const float*)d_in[7];
    const float* w_v  = (const float*)d_in[8];
    const float* b_v  = (const float*)d_in[9];
    const float* w_o  = (const float*)d_in[10];
    const float* b_o  = (const float*)d_in[11];
    float* out = (float*)d_out;

    float *gQ, *gK, *gV, *gC;
    cudaGetSymbolAddress((void**)&gQ, g_Q);
    cudaGetSymbolAddress((void**)&gK, g_K);
    cudaGetSymbolAddress((void**)&gV, g_V);
    cudaGetSymbolAddress((void**)&gC, g_C);

    cudaFuncSetAttribute(attn_kernel,
                         cudaFuncAttributeMaxDynamicSharedMemorySize,
                         ATTN_SMEM_BYTES);

    dim3 gblk(256);
    dim3 ggrid(D_ / GBN, M_ / GBM);   // (8, 32)

    gemm_bias_kernel<<<ggrid, gblk>>>(q, w_q, b_q, gQ, M_, D_, D_);
    gemm_bias_kernel<<<ggrid, gblk>>>(k, w_k, b_k, gK, M_, D_, D_);
    gemm_bias_kernel<<<ggrid, gblk>>>(v, w_v, b_v, gV, M_, D_, D_);

    dim3 ablk(256);
    dim3 agrid(S_ / TQ, B_ * H_);     // (32, 32)
    attn_kernel<<<agrid, ablk, ATTN_SMEM_BYTES>>>(gQ, gK, gV, mask, gC);

    gemm_bias_kernel<<<ggrid, gblk>>>(gC, w_o, b_o, out, M_, D_, D_);
}

// round 4
// speedup vs baseline: 1.2581x; 1.2581x over previous
#include <cuda_runtime.h>
#include <cuda_bf16.h>
#include <cstdint>

// Problem constants
#define B_  2
#define S_  2048
#define D_  1024
#define H_  16
#define DK_ 64
#define M_  (B_ * S_)   // 4096

// ---------------------------------------------------------------------------
// Scratch
// ---------------------------------------------------------------------------
__device__ float g_Q[M_ * D_];
__device__ float g_K[M_ * D_];
__device__ float g_V[M_ * D_];
__device__ float g_C[M_ * D_];

__device__ __forceinline__ uint32_t smem_u32(const void* p) {
    uint32_t a;
    asm("{ .reg .u64 t; cvta.to.shared.u64 t, %1; cvt.u32.u64 %0, t; }"
        : "=r"(a) : "l"(p));
    return a;
}

// Ampere-style bf16 MMA (PTX sm_80+, no 'a'-feature needed -> works on compute_103)
__device__ __forceinline__ void mma16816(float& c0, float& c1, float& c2, float& c3,
                                         uint32_t a0, uint32_t a1, uint32_t a2, uint32_t a3,
                                         uint32_t b0, uint32_t b1) {
    asm volatile(
        "mma.sync.aligned.m16n8k16.row.col.f32.bf16.bf16.f32 "
        "{%0,%1,%2,%3}, {%4,%5,%6,%7}, {%8,%9}, {%0,%1,%2,%3};"
        : "+f"(c0), "+f"(c1), "+f"(c2), "+f"(c3)
        : "r"(a0), "r"(a1), "r"(a2), "r"(a3), "r"(b0), "r"(b1));
}

__device__ __forceinline__ void ldsm4(uint32_t& r0, uint32_t& r1, uint32_t& r2, uint32_t& r3,
                                      uint32_t addr) {
    asm volatile("ldmatrix.sync.aligned.m8n8.x4.shared.b16 {%0,%1,%2,%3}, [%4];"
                 : "=r"(r0), "=r"(r1), "=r"(r2), "=r"(r3) : "r"(addr));
}

union PackB4 { uint64_t u; __nv_bfloat16 b[4]; };

__device__ __forceinline__ void split4(float4 v, uint64_t& hi, uint64_t& lo) {
    PackB4 h, l;
    h.b[0] = __float2bfloat16_rn(v.x);
    h.b[1] = __float2bfloat16_rn(v.y);
    h.b[2] = __float2bfloat16_rn(v.z);
    h.b[3] = __float2bfloat16_rn(v.w);
    l.b[0] = __float2bfloat16_rn(v.x - __bfloat162float(h.b[0]));
    l.b[1] = __float2bfloat16_rn(v.y - __bfloat162float(h.b[1]));
    l.b[2] = __float2bfloat16_rn(v.z - __bfloat162float(h.b[2]));
    l.b[3] = __float2bfloat16_rn(v.w - __bfloat162float(h.b[3]));
    hi = h.u; lo = l.u;
}

// ===========================================================================
// Split-bf16 mma.sync GEMM+bias: Y[M,1024] = X[M,1024] @ W[1024,1024]^T + b
// CTA 128x128, BK=32, 256 threads = 8 warps (2m x 4n), warp tile 64x32.
// Compensation: Y ~= Ah*Bh + Ah*Bl + Al*Bh  (fp32 accum in MMA).
// ===========================================================================
#define BM 128
#define BN 128
#define BK 32
#define LDAB 40   // bf16 elems per smem row (80 bytes; 80/16=5 -> ldmatrix conflict-free)

__global__ __launch_bounds__(256, 2) void gemm_mma_kernel(
    const float* __restrict__ X, const float* __restrict__ W,
    const float* __restrict__ bias, float* __restrict__ Y)
{
    __shared__ __align__(128) __nv_bfloat16 sAh[BM * LDAB];
    __shared__ __align__(128) __nv_bfloat16 sAl[BM * LDAB];
    __shared__ __align__(128) __nv_bfloat16 sBh[BN * LDAB];
    __shared__ __align__(128) __nv_bfloat16 sBl[BN * LDAB];

    const int tid  = threadIdx.x;
    const int lane = tid & 31;
    const int wid  = tid >> 5;
    const int wm   = wid >> 2;         // 0..1 -> m offset wm*64
    const int wn   = wid & 3;          // 0..3 -> n offset wn*32
    const int m0 = blockIdx.y * BM;
    const int n0 = blockIdx.x * BN;

    const uint32_t bAh = smem_u32(sAh);
    const uint32_t bAl = smem_u32(sAl);
    const uint32_t bBh = smem_u32(sBh);
    const uint32_t bBl = smem_u32(sBl);

    // ldmatrix per-lane offsets
    // A x4: lanes0-7 rows0-7@k0, 8-15 rows8-15@k0, 16-23 rows0-7@k8, 24-31 rows8-15@k8
    const uint32_t aoff = (uint32_t)((lane & 15) * 80 + (lane >> 4) * 16);
    // B x4 (2 n-tiles): lanes0-7 n0-7@k0, 8-15 n0-7@k8, 16-23 n8-15@k0, 24-31 n8-15@k8
    const uint32_t boff = (uint32_t)(((lane & 7) + ((lane >> 4) & 1) * 8) * 80 +
                                     (((lane >> 3) & 1) ? 16 : 0));

    // loader mapping: 256 threads, each does 4 rows x 1 float4-col per matrix
    const int lr = tid >> 3;          // 0..31 base row
    const int lc = tid & 7;           // float4 col (0..7) -> k cols lc*4

    float C[4][4][4];
#pragma unroll
    for (int i = 0; i < 4; i++)
#pragma unroll
        for (int j = 0; j < 4; j++)
#pragma unroll
            for (int t = 0; t < 4; t++) C[i][j][t] = 0.0f;

    for (int k0 = 0; k0 < D_; k0 += BK) {
        __syncthreads();
        // Load + split X and W tiles into smem (bf16 hi/lo)
#pragma unroll
        for (int it = 0; it < 4; it++) {
            const int r = lr + it * 32;
            uint64_t hi, lo;
            float4 xv = *(const float4*)&X[(size_t)(m0 + r) * D_ + k0 + lc * 4];
            split4(xv, hi, lo);
            *(uint64_t*)((char*)sAh + r * 80 + lc * 8) = hi;
            *(uint64_t*)((char*)sAl + r * 80 + lc * 8) = lo;
            float4 wv = *(const float4*)&W[(size_t)(n0 + r) * D_ + k0 + lc * 4];
            split4(wv, hi, lo);
            *(uint64_t*)((char*)sBh + r * 80 + lc * 8) = hi;
            *(uint64_t*)((char*)sBl + r * 80 + lc * 8) = lo;
        }
        __syncthreads();

#pragma unroll
        for (int ks = 0; ks < 2; ks++) {
            const uint32_t kbyte = (uint32_t)(ks * 32);
            uint32_t bh[2][4], bl[2][4];
#pragma unroll
            for (int p = 0; p < 2; p++) {
                ldsm4(bh[p][0], bh[p][1], bh[p][2], bh[p][3],
                      bBh + (uint32_t)((wn * 32 + p * 16) * 80) + kbyte + boff);
                ldsm4(bl[p][0], bl[p][1], bl[p][2], bl[p][3],
                      bBl + (uint32_t)((wn * 32 + p * 16) * 80) + kbyte + boff);
            }
            {
                uint32_t a[4][4];
#pragma unroll
                for (int i = 0; i < 4; i++)
                    ldsm4(a[i][0], a[i][1], a[i][2], a[i][3],
                          bAh + (uint32_t)((wm * 64 + i * 16) * 80) + kbyte + aoff);
#pragma unroll
                for (int i = 0; i < 4; i++)
#pragma unroll
                    for (int j = 0; j < 4; j++) {
                        mma16816(C[i][j][0], C[i][j][1], C[i][j][2], C[i][j][3],
                                 a[i][0], a[i][1], a[i][2], a[i][3],
                                 bh[j >> 1][(j & 1) * 2], bh[j >> 1][(j & 1) * 2 + 1]);
                        mma16816(C[i][j][0], C[i][j][1], C[i][j][2], C[i][j][3],
                                 a[i][0], a[i][1], a[i][2], a[i][3],
                                 bl[j >> 1][(j & 1) * 2], bl[j >> 1][(j & 1) * 2 + 1]);
                    }
            }
            {
                uint32_t a[4][4];
#pragma unroll
                for (int i = 0; i < 4; i++)
                    ldsm4(a[i][0], a[i][1], a[i][2], a[i][3],
                          bAl + (uint32_t)((wm * 64 + i * 16) * 80) + kbyte + aoff);
#pragma unroll
                for (int i = 0; i < 4; i++)
#pragma unroll
                    for (int j = 0; j < 4; j++)
                        mma16816(C[i][j][0], C[i][j][1], C[i][j][2], C[i][j][3],
                                 a[i][0], a[i][1], a[i][2], a[i][3],
                                 bh[j >> 1][(j & 1) * 2], bh[j >> 1][(j & 1) * 2 + 1]);
            }
        }
    }

    // Epilogue: frag mapping: rows = base + lane/4 (+8), cols = base + (lane%4)*2
    const int qr = lane >> 2;
    const int qc = (lane & 3) * 2;
#pragma unroll
    for (int i = 0; i < 4; i++) {
        const int row0 = m0 + wm * 64 + i * 16 + qr;
#pragma unroll
        for (int j = 0; j < 4; j++) {
            const int col = n0 + wn * 32 + j * 8 + qc;
            const float b0v = bias[col], b1v = bias[col + 1];
            float2 o0 = { C[i][j][0] + b0v, C[i][j][1] + b1v };
            float2 o1 = { C[i][j][2] + b0v, C[i][j][3] + b1v };
            *(float2*)&Y[(size_t)row0 * D_ + col]       = o0;
            *(float2*)&Y[(size_t)(row0 + 8) * D_ + col] = o1;
        }
    }
}

// ---------------------------------------------------------------------------
// Fused attention (flash-style online softmax) — unchanged from R2 (passed).
// ---------------------------------------------------------------------------
#define TQ 64
#define TK 64
#define LDP 68
#define ATTN_SMEM_FLOATS (4 * TQ * LDP + 3 * TQ)
#define ATTN_SMEM_BYTES  (ATTN_SMEM_FLOATS * 4)

__global__ __launch_bounds__(256) void attn_kernel(
    const float* __restrict__ Q, const float* __restrict__ K,
    const float* __restrict__ V, const int* __restrict__ mask,
    float* __restrict__ C)
{
    extern __shared__ float smemf[];
    float (*sQ)[LDP] = (float (*)[LDP])(smemf);
    float (*sK)[LDP] = (float (*)[LDP])(smemf + 1 * TQ * LDP);
    float (*sV)[LDP] = (float (*)[LDP])(smemf + 2 * TQ * LDP);
    float (*sS)[LDP] = (float (*)[LDP])(smemf + 3 * TQ * LDP);
    float* sM    = smemf + 4 * TQ * LDP;
    float* sL    = sM + TQ;
    float* sCorr = sL + TQ;

    const int tid = threadIdx.x;
    const int tx = tid & 15;
    const int ty = tid >> 4;
    const int bh = blockIdx.y;
    const int b  = bh / H_;
    const int h  = bh % H_;
    const int q0 = blockIdx.x * TQ;

    const float* Qb = Q + (size_t)b * S_ * D_ + (size_t)h * DK_;
    const float* Kb = K + (size_t)b * S_ * D_ + (size_t)h * DK_;
    const float* Vb = V + (size_t)b * S_ * D_ + (size_t)h * DK_;
    const int*   Mb = mask + (size_t)b * S_ * S_;

#pragma unroll
    for (int i = 0; i < 4; i++) {
        int idx = tid + i * 256;
        int r  = idx >> 4;
        int c4 = idx & 15;
        *(float4*)&sQ[r][c4 * 4] =
            *(const float4*)&Qb[(size_t)(q0 + r) * D_ + c4 * 4];
    }
    if (tid < TQ) { sM[tid] = -1e30f; sL[tid] = 0.0f; }

    float o[4][4];
#pragma unroll
    for (int i = 0; i < 4; i++)
#pragma unroll
        for (int j = 0; j < 4; j++) o[i][j] = 0.0f;

    __syncthreads();

    for (int k0 = 0; k0 < S_; k0 += TK) {
#pragma unroll
        for (int i = 0; i < 4; i++) {
            int idx = tid + i * 256;
            int r  = idx >> 4;
            int c4 = idx & 15;
            *(float4*)&sK[r][c4 * 4] =
                *(const float4*)&Kb[(size_t)(k0 + r) * D_ + c4 * 4];
            *(float4*)&sV[r][c4 * 4] =
                *(const float4*)&Vb[(size_t)(k0 + r) * D_ + c4 * 4];
        }
        __syncthreads();

        float s[4][4];
#pragma unroll
        for (int i = 0; i < 4; i++)
#pragma unroll
            for (int j = 0; j < 4; j++) s[i][j] = 0.0f;

#pragma unroll
        for (int d = 0; d < DK_; d++) {
            float a[4], bb[4];
#pragma unroll
            for (int i = 0; i < 4; i++) a[i]  = sQ[ty * 4 + i][d];
#pragma unroll
            for (int j = 0; j < 4; j++) bb[j] = sK[tx * 4 + j][d];
#pragma unroll
            for (int i = 0; i < 4; i++)
#pragma unroll
                for (int j = 0; j < 4; j++)
                    s[i][j] += a[i] * bb[j];
        }

#pragma unroll
        for (int i = 0; i < 4; i++) {
            int qr = q0 + ty * 4 + i;
            int4 mrow = *(const int4*)&Mb[(size_t)qr * S_ + k0 + tx * 4];
            float v0 = s[i][0] * 0.125f;
            float v1 = s[i][1] * 0.125f;
            float v2 = s[i][2] * 0.125f;
            float v3 = s[i][3] * 0.125f;
            if (mrow.x == 0) v0 = -1e9f;
            if (mrow.y == 0) v1 = -1e9f;
            if (mrow.z == 0) v2 = -1e9f;
            if (mrow.w == 0) v3 = -1e9f;
            sS[ty * 4 + i][tx * 4 + 0] = v0;
            sS[ty * 4 + i][tx * 4 + 1] = v1;
            sS[ty * 4 + i][tx * 4 + 2] = v2;
            sS[ty * 4 + i][tx * 4 + 3] = v3;
        }
        __syncthreads();

        {
            int r = tid >> 2;
            int g = tid & 3;
            float rowmax = -1e30f;
#pragma unroll
            for (int c = 0; c < 16; c++)
                rowmax = fmaxf(rowmax, sS[r][g * 16 + c]);
            rowmax = fmaxf(rowmax, __shfl_xor_sync(0xFFFFFFFF, rowmax, 1));
            rowmax = fmaxf(rowmax, __shfl_xor_sync(0xFFFFFFFF, rowmax, 2));
            float mprev = sM[r];
            float nm = fmaxf(mprev, rowmax);
            float sum = 0.0f;
#pragma unroll
            for (int c = 0; c < 16; c++) {
                float p = __expf(sS[r][g * 16 + c] - nm);
                sS[r][g * 16 + c] = p;
                sum += p;
            }
            sum += __shfl_xor_sync(0xFFFFFFFF, sum, 1);
            sum += __shfl_xor_sync(0xFFFFFFFF, sum, 2);
            if (g == 0) {
                float corr = __expf(mprev - nm);
                sL[r] = sL[r] * corr + sum;
                sM[r] = nm;
                sCorr[r] = corr;
            }
        }
        __syncthreads();

        float cr[4];
#pragma unroll
        for (int i = 0; i < 4; i++) cr[i] = sCorr[ty * 4 + i];
#pragma unroll
        for (int i = 0; i < 4; i++)
#pragma unroll
            for (int j = 0; j < 4; j++) o[i][j] *= cr[i];

#pragma unroll
        for (int kk = 0; kk < TK; kk++) {
            float p[4], vv[4];
#pragma unroll
            for (int i = 0; i < 4; i++) p[i]  = sS[ty * 4 + i][kk];
#pragma unroll
            for (int j = 0; j < 4; j++) vv[j] = sV[kk][tx * 4 + j];
#pragma unroll
            for (int i = 0; i < 4; i++)
#pragma unroll
                for (int j = 0; j < 4; j++)
                    o[i][j] += p[i] * vv[j];
        }
        __syncthreads();
    }

    float inv[4];
#pragma unroll
    for (int i = 0; i < 4; i++) inv[i] = 1.0f / sL[ty * 4 + i];

    float* Cb = C + (size_t)b * S_ * D_ + (size_t)h * DK_;
#pragma unroll
    for (int i = 0; i < 4; i++) {
        int qr = q0 + ty * 4 + i;
        float4 ov;
        ov.x = o[i][0] * inv[i];
        ov.y = o[i][1] * inv[i];
        ov.z = o[i][2] * inv[i];
        ov.w = o[i][3] * inv[i];
        *(float4*)&Cb[(size_t)qr * D_ + tx * 4] = ov;
    }
}

// ---------------------------------------------------------------------------
// Launch
// ---------------------------------------------------------------------------
extern "C" void kernel_launch(void* const* d_in, const int* in_sizes, int n_in,
                              void* d_out, int out_size)
{
    (void)in_sizes; (void)n_in; (void)out_size;
    const float* q    = (const float*)d_in[0];
    const float* k    = (const float*)d_in[1];
    const float* v    = (const float*)d_in[2];
    const int*   mask = (const int*)d_in[3];
    const float* w_q  = (const float*)d_in[4];
    const float* b_q  = (const float*)d_in[5];
    const float* w_k  = (const float*)d_in[6];
    const float* b_k  = (const float*)d_in[7];
    const float* w_v  = (const float*)d_in[8];
    const float* b_v  = (const float*)d_in[9];
    const float* w_o  = (const float*)d_in[10];
    const float* b_o  = (const float*)d_in[11];
    float* out = (float*)d_out;

    float *gQ, *gK, *gV, *gC;
    cudaGetSymbolAddress((void**)&gQ, g_Q);
    cudaGetSymbolAddress((void**)&gK, g_K);
    cudaGetSymbolAddress((void**)&gV, g_V);
    cudaGetSymbolAddress((void**)&gC, g_C);

    cudaFuncSetAttribute(attn_kernel,
                         cudaFuncAttributeMaxDynamicSharedMemorySize,
                         ATTN_SMEM_BYTES);

    dim3 gblk(256);
    dim3 ggrid(D_ / BN, M_ / BM);     // (8, 32)

    gemm_mma_kernel<<<ggrid, gblk>>>(q, w_q, b_q, gQ);
    gemm_mma_kernel<<<ggrid, gblk>>>(k, w_k, b_k, gK);
    gemm_mma_kernel<<<ggrid, gblk>>>(v, w_v, b_v, gV);

    dim3 ablk(256);
    dim3 agrid(S_ / TQ, B_ * H_);     // (32, 32)
    attn_kernel<<<agrid, ablk, ATTN_SMEM_BYTES>>>(gQ, gK, gV, mask, gC);

    gemm_mma_kernel<<<ggrid, gblk>>>(gC, w_o, b_o, out);
}

// round 5
// speedup vs baseline: 2.2035x; 1.7514x over previous
#include <cuda_runtime.h>
#include <cuda_bf16.h>
#include <cstdint>

// Problem constants
#define B_  2
#define S_  2048
#define D_  1024
#define H_  16
#define DK_ 64
#define M_  (B_ * S_)   // 4096

// ---------------------------------------------------------------------------
// Scratch
// ---------------------------------------------------------------------------
__device__ float g_Q[M_ * D_];
__device__ float g_K[M_ * D_];
__device__ float g_V[M_ * D_];
__device__ float g_C[M_ * D_];

__device__ __forceinline__ uint32_t smem_u32(const void* p) {
    uint32_t a;
    asm("{ .reg .u64 t; cvta.to.shared.u64 t, %1; cvt.u32.u64 %0, t; }"
        : "=r"(a) : "l"(p));
    return a;
}

// bf16 MMA m16n8k16 (sm_80+ PTX -> valid on compute_103)
__device__ __forceinline__ void mma16816(float* c,
                                         uint32_t a0, uint32_t a1, uint32_t a2, uint32_t a3,
                                         uint32_t b0, uint32_t b1) {
    asm volatile(
        "mma.sync.aligned.m16n8k16.row.col.f32.bf16.bf16.f32 "
        "{%0,%1,%2,%3}, {%4,%5,%6,%7}, {%8,%9}, {%0,%1,%2,%3};"
        : "+f"(c[0]), "+f"(c[1]), "+f"(c[2]), "+f"(c[3])
        : "r"(a0), "r"(a1), "r"(a2), "r"(a3), "r"(b0), "r"(b1));
}

__device__ __forceinline__ void ldsm4(uint32_t& r0, uint32_t& r1, uint32_t& r2, uint32_t& r3,
                                      uint32_t addr) {
    asm volatile("ldmatrix.sync.aligned.m8n8.x4.shared.b16 {%0,%1,%2,%3}, [%4];"
                 : "=r"(r0), "=r"(r1), "=r"(r2), "=r"(r3) : "r"(addr));
}

__device__ __forceinline__ void ldsm4t(uint32_t& r0, uint32_t& r1, uint32_t& r2, uint32_t& r3,
                                       uint32_t addr) {
    asm volatile("ldmatrix.sync.aligned.m8n8.x4.trans.shared.b16 {%0,%1,%2,%3}, [%4];"
                 : "=r"(r0), "=r"(r1), "=r"(r2), "=r"(r3) : "r"(addr));
}

union PackB4 { uint64_t u; __nv_bfloat16 b[4]; };

__device__ __forceinline__ void split4(float4 v, uint64_t& hi, uint64_t& lo) {
    PackB4 h, l;
    h.b[0] = __float2bfloat16_rn(v.x);
    h.b[1] = __float2bfloat16_rn(v.y);
    h.b[2] = __float2bfloat16_rn(v.z);
    h.b[3] = __float2bfloat16_rn(v.w);
    l.b[0] = __float2bfloat16_rn(v.x - __bfloat162float(h.b[0]));
    l.b[1] = __float2bfloat16_rn(v.y - __bfloat162float(h.b[1]));
    l.b[2] = __float2bfloat16_rn(v.z - __bfloat162float(h.b[2]));
    l.b[3] = __float2bfloat16_rn(v.w - __bfloat162float(h.b[3]));
    hi = h.u; lo = l.u;
}

__device__ __forceinline__ uint32_t packbf(float lo, float hi) {
    __nv_bfloat162 t = __floats2bfloat162_rn(lo, hi);
    return *(uint32_t*)&t;
}

// ===========================================================================
// Split-bf16 mma.sync GEMM+bias (unchanged from R4 — passed, ~100us each)
// ===========================================================================
#define BM 128
#define BN 128
#define BK 32

__global__ __launch_bounds__(256, 2) void gemm_mma_kernel(
    const float* __restrict__ X, const float* __restrict__ W,
    const float* __restrict__ bias, float* __restrict__ Y)
{
    __shared__ __align__(128) __nv_bfloat16 sAh[BM * 40];
    __shared__ __align__(128) __nv_bfloat16 sAl[BM * 40];
    __shared__ __align__(128) __nv_bfloat16 sBh[BN * 40];
    __shared__ __align__(128) __nv_bfloat16 sBl[BN * 40];

    const int tid  = threadIdx.x;
    const int lane = tid & 31;
    const int wid  = tid >> 5;
    const int wm   = wid >> 2;
    const int wn   = wid & 3;
    const int m0 = blockIdx.y * BM;
    const int n0 = blockIdx.x * BN;

    const uint32_t bAh = smem_u32(sAh);
    const uint32_t bAl = smem_u32(sAl);
    const uint32_t bBh = smem_u32(sBh);
    const uint32_t bBl = smem_u32(sBl);

    const uint32_t aoff = (uint32_t)((lane & 15) * 80 + (lane >> 4) * 16);
    const uint32_t boff = (uint32_t)(((lane & 7) + ((lane >> 4) & 1) * 8) * 80 +
                                     (((lane >> 3) & 1) ? 16 : 0));

    const int lr = tid >> 3;
    const int lc = tid & 7;

    float C[4][4][4];
#pragma unroll
    for (int i = 0; i < 4; i++)
#pragma unroll
        for (int j = 0; j < 4; j++)
#pragma unroll
            for (int t = 0; t < 4; t++) C[i][j][t] = 0.0f;

    for (int k0 = 0; k0 < D_; k0 += BK) {
        __syncthreads();
#pragma unroll
        for (int it = 0; it < 4; it++) {
            const int r = lr + it * 32;
            uint64_t hi, lo;
            float4 xv = *(const float4*)&X[(size_t)(m0 + r) * D_ + k0 + lc * 4];
            split4(xv, hi, lo);
            *(uint64_t*)((char*)sAh + r * 80 + lc * 8) = hi;
            *(uint64_t*)((char*)sAl + r * 80 + lc * 8) = lo;
            float4 wv = *(const float4*)&W[(size_t)(n0 + r) * D_ + k0 + lc * 4];
            split4(wv, hi, lo);
            *(uint64_t*)((char*)sBh + r * 80 + lc * 8) = hi;
            *(uint64_t*)((char*)sBl + r * 80 + lc * 8) = lo;
        }
        __syncthreads();

#pragma unroll
        for (int ks = 0; ks < 2; ks++) {
            const uint32_t kbyte = (uint32_t)(ks * 32);
            uint32_t bh[2][4], bl[2][4];
#pragma unroll
            for (int p = 0; p < 2; p++) {
                ldsm4(bh[p][0], bh[p][1], bh[p][2], bh[p][3],
                      bBh + (uint32_t)((wn * 32 + p * 16) * 80) + kbyte + boff);
                ldsm4(bl[p][0], bl[p][1], bl[p][2], bl[p][3],
                      bBl + (uint32_t)((wn * 32 + p * 16) * 80) + kbyte + boff);
            }
            {
                uint32_t a[4][4];
#pragma unroll
                for (int i = 0; i < 4; i++)
                    ldsm4(a[i][0], a[i][1], a[i][2], a[i][3],
                          bAh + (uint32_t)((wm * 64 + i * 16) * 80) + kbyte + aoff);
#pragma unroll
                for (int i = 0; i < 4; i++)
#pragma unroll
                    for (int j = 0; j < 4; j++) {
                        mma16816(C[i][j], a[i][0], a[i][1], a[i][2], a[i][3],
                                 bh[j >> 1][(j & 1) * 2], bh[j >> 1][(j & 1) * 2 + 1]);
                        mma16816(C[i][j], a[i][0], a[i][1], a[i][2], a[i][3],
                                 bl[j >> 1][(j & 1) * 2], bl[j >> 1][(j & 1) * 2 + 1]);
                    }
            }
            {
                uint32_t a[4][4];
#pragma unroll
                for (int i = 0; i < 4; i++)
                    ldsm4(a[i][0], a[i][1], a[i][2], a[i][3],
                          bAl + (uint32_t)((wm * 64 + i * 16) * 80) + kbyte + aoff);
#pragma unroll
                for (int i = 0; i < 4; i++)
#pragma unroll
                    for (int j = 0; j < 4; j++)
                        mma16816(C[i][j], a[i][0], a[i][1], a[i][2], a[i][3],
                                 bh[j >> 1][(j & 1) * 2], bh[j >> 1][(j & 1) * 2 + 1]);
            }
        }
    }

    const int qr = lane >> 2;
    const int qc = (lane & 3) * 2;
#pragma unroll
    for (int i = 0; i < 4; i++) {
        const int row0 = m0 + wm * 64 + i * 16 + qr;
#pragma unroll
        for (int j = 0; j < 4; j++) {
            const int col = n0 + wn * 32 + j * 8 + qc;
            const float b0v = bias[col], b1v = bias[col + 1];
            float2 o0 = { C[i][j][0] + b0v, C[i][j][1] + b1v };
            float2 o1 = { C[i][j][2] + b0v, C[i][j][3] + b1v };
            *(float2*)&Y[(size_t)row0 * D_ + col]       = o0;
            *(float2*)&Y[(size_t)(row0 + 8) * D_ + col] = o1;
        }
    }
}

// ===========================================================================
// Flash attention with split-bf16 mma.sync.
// CTA: 128 query rows x one (b,h). 8 warps, 16 rows each. K-tiles of 64.
// smem: Q/K/V bf16 hi/lo, 144B row stride (36 words -> ldmatrix conflict-free).
// ===========================================================================
#define ATQ 128
#define ATK 64
#define ALD 144   // bytes per smem row (72 bf16 slots, 64 used)

#define AOFF_QH 0
#define AOFF_QL (AOFF_QH + ATQ * ALD)     // 18432
#define AOFF_KH (AOFF_QL + ATQ * ALD)     // 36864
#define AOFF_KL (AOFF_KH + ATK * ALD)     // 46080
#define AOFF_VH (AOFF_KL + ATK * ALD)     // 55296
#define AOFF_VL (AOFF_VH + ATK * ALD)     // 64512
#define ATTN_SMEM_BYTES (AOFF_VL + ATK * ALD)  // 73728

__global__ __launch_bounds__(256) void attn_mma_kernel(
    const float* __restrict__ Q, const float* __restrict__ K,
    const float* __restrict__ V, const int* __restrict__ mask,
    float* __restrict__ C)
{
    extern __shared__ __align__(128) char smem[];
    const uint32_t sb = smem_u32(smem);

    const int tid  = threadIdx.x;
    const int lane = tid & 31;
    const int wid  = tid >> 5;        // 0..7, warp owns rows [wid*16, wid*16+16)
    const int bh = blockIdx.y;
    const int b  = bh >> 4;
    const int h  = bh & 15;
    const int q0 = blockIdx.x * ATQ;

    const float* Qb = Q + (size_t)b * S_ * D_ + (size_t)h * DK_;
    const float* Kb = K + (size_t)b * S_ * D_ + (size_t)h * DK_;
    const float* Vb = V + (size_t)b * S_ * D_ + (size_t)h * DK_;
    const int*   Mb = mask + (size_t)b * S_ * S_;

    // ---- load Q tile (128 x 64), split hi/lo ----
    {
        const int lr = tid >> 4;      // used with +16 stride below? (2048 float4 total)
        const int lc = tid & 15;
#pragma unroll
        for (int i = 0; i < 8; i++) {
            const int r = lr + i * 16;
            float4 qv = *(const float4*)&Qb[(size_t)(q0 + r) * D_ + lc * 4];
            uint64_t hi, lo;
            split4(qv, hi, lo);
            *(uint64_t*)(smem + AOFF_QH + r * ALD + lc * 8) = hi;
            *(uint64_t*)(smem + AOFF_QL + r * ALD + lc * 8) = lo;
        }
    }

    // ldmatrix per-lane offsets
    const uint32_t aoffQ = sb + (uint32_t)((wid * 16 + (lane & 15)) * ALD + (lane >> 4) * 16);
    const uint32_t boffK = sb + (uint32_t)(((lane & 7) + ((lane >> 4) & 1) * 8) * ALD +
                                           ((lane >> 3) & 1) * 16);
    const uint32_t voffV = sb + (uint32_t)((((lane >> 3) & 1) * 8 + (lane & 7)) * ALD +
                                           ((lane >> 4) & 1) * 16);

    // per-thread softmax row state: rows r0 = q0+wid*16+lane/4, r0+8
    float mstate[2] = { -1e30f, -1e30f };
    float lstate[2] = { 0.0f, 0.0f };
    float O[8][4];
#pragma unroll
    for (int j = 0; j < 8; j++)
#pragma unroll
        for (int t = 0; t < 4; t++) O[j][t] = 0.0f;

    const int row0 = q0 + wid * 16 + (lane >> 2);
    const int mcol = (lane & 3) * 2;
    const int* mrow0 = Mb + (size_t)row0 * S_;
    const int* mrow1 = Mb + (size_t)(row0 + 8) * S_;

    const int lr = tid >> 4;   // K/V loader: rows 0..15 (+16 per iter), 1024 float4
    const int lc = tid & 15;

    for (int k0 = 0; k0 < S_; k0 += ATK) {
        __syncthreads();   // smem safe to overwrite (covers Q-store on first iter)
        // ---- load K,V tiles (64 x 64 each), split hi/lo ----
#pragma unroll
        for (int i = 0; i < 4; i++) {
            const int r = lr + i * 16;
            uint64_t hi, lo;
            float4 kv = *(const float4*)&Kb[(size_t)(k0 + r) * D_ + lc * 4];
            split4(kv, hi, lo);
            *(uint64_t*)(smem + AOFF_KH + r * ALD + lc * 8) = hi;
            *(uint64_t*)(smem + AOFF_KL + r * ALD + lc * 8) = lo;
            float4 vv = *(const float4*)&Vb[(size_t)(k0 + r) * D_ + lc * 4];
            split4(vv, hi, lo);
            *(uint64_t*)(smem + AOFF_VH + r * ALD + lc * 8) = hi;
            *(uint64_t*)(smem + AOFF_VL + r * ALD + lc * 8) = lo;
        }
        __syncthreads();

        // ---- S = Q K^T (split compensated), 16x64 per warp ----
        float Sf[8][4];
#pragma unroll
        for (int j = 0; j < 8; j++)
#pragma unroll
            for (int t = 0; t < 4; t++) Sf[j][t] = 0.0f;

#pragma unroll
        for (int kc = 0; kc < 4; kc++) {
            const uint32_t kb = (uint32_t)(kc * 32);
            uint32_t ah[4], al[4];
            ldsm4(ah[0], ah[1], ah[2], ah[3], aoffQ + AOFF_QH + kb);
            ldsm4(al[0], al[1], al[2], al[3], aoffQ + AOFF_QL + kb);
#pragma unroll
            for (int jp = 0; jp < 4; jp++) {
                uint32_t kh[4], kl[4];
                ldsm4(kh[0], kh[1], kh[2], kh[3],
                      boffK + AOFF_KH + (uint32_t)(jp * 16 * ALD) + kb);
                ldsm4(kl[0], kl[1], kl[2], kl[3],
                      boffK + AOFF_KL + (uint32_t)(jp * 16 * ALD) + kb);
                mma16816(Sf[jp * 2],     ah[0], ah[1], ah[2], ah[3], kh[0], kh[1]);
                mma16816(Sf[jp * 2],     ah[0], ah[1], ah[2], ah[3], kl[0], kl[1]);
                mma16816(Sf[jp * 2],     al[0], al[1], al[2], al[3], kh[0], kh[1]);
                mma16816(Sf[jp * 2 + 1], ah[0], ah[1], ah[2], ah[3], kh[2], kh[3]);
                mma16816(Sf[jp * 2 + 1], ah[0], ah[1], ah[2], ah[3], kl[2], kl[3]);
                mma16816(Sf[jp * 2 + 1], al[0], al[1], al[2], al[3], kh[2], kh[3]);
            }
        }

        // ---- scale + mask ----
#pragma unroll
        for (int j = 0; j < 8; j++) {
            int2 mv0 = *(const int2*)&mrow0[k0 + j * 8 + mcol];
            int2 mv1 = *(const int2*)&mrow1[k0 + j * 8 + mcol];
            Sf[j][0] = (mv0.x == 0) ? -1e9f : Sf[j][0] * 0.125f;
            Sf[j][1] = (mv0.y == 0) ? -1e9f : Sf[j][1] * 0.125f;
            Sf[j][2] = (mv1.x == 0) ? -1e9f : Sf[j][2] * 0.125f;
            Sf[j][3] = (mv1.y == 0) ? -1e9f : Sf[j][3] * 0.125f;
        }

        // ---- online softmax (2 rows per thread, 4-lane groups) ----
        float corr[2];
#pragma unroll
        for (int rr = 0; rr < 2; rr++) {
            float mx = -1e30f;
#pragma unroll
            for (int j = 0; j < 8; j++)
                mx = fmaxf(mx, fmaxf(Sf[j][rr * 2], Sf[j][rr * 2 + 1]));
            mx = fmaxf(mx, __shfl_xor_sync(0xFFFFFFFF, mx, 1));
            mx = fmaxf(mx, __shfl_xor_sync(0xFFFFFFFF, mx, 2));
            float mnew = fmaxf(mstate[rr], mx);
            corr[rr] = __expf(mstate[rr] - mnew);
            float sum = 0.0f;
#pragma unroll
            for (int j = 0; j < 8; j++) {
                float p0 = __expf(Sf[j][rr * 2]     - mnew);
                float p1 = __expf(Sf[j][rr * 2 + 1] - mnew);
                Sf[j][rr * 2] = p0; Sf[j][rr * 2 + 1] = p1;
                sum += p0 + p1;
            }
            sum += __shfl_xor_sync(0xFFFFFFFF, sum, 1);
            sum += __shfl_xor_sync(0xFFFFFFFF, sum, 2);
            lstate[rr] = lstate[rr] * corr[rr] + sum;
            mstate[rr] = mnew;
        }

        // rescale O
#pragma unroll
        for (int j = 0; j < 8; j++) {
            O[j][0] *= corr[0]; O[j][1] *= corr[0];
            O[j][2] *= corr[1]; O[j][3] *= corr[1];
        }

        // ---- pack P into A-fragments (hi/lo split) ----
        uint32_t aPh[4][4], aPl[4][4];
#pragma unroll
        for (int kc = 0; kc < 4; kc++) {
#pragma unroll
            for (int half = 0; half < 2; half++) {       // ntile 2kc+half
                const int j = kc * 2 + half;
#pragma unroll
                for (int rr = 0; rr < 2; rr++) {
                    float p0 = Sf[j][rr * 2], p1 = Sf[j][rr * 2 + 1];
                    __nv_bfloat16 h0 = __float2bfloat16_rn(p0);
                    __nv_bfloat16 h1 = __float2bfloat16_rn(p1);
                    float l0 = p0 - __bfloat162float(h0);
                    float l1 = p1 - __bfloat162float(h1);
                    __nv_bfloat162 hp; hp.x = h0; hp.y = h1;
                    aPh[kc][half * 2 + rr] = *(uint32_t*)&hp;
                    aPl[kc][half * 2 + rr] = packbf(l0, l1);
                }
            }
        }

        // ---- O += P V (split compensated) ----
#pragma unroll
        for (int kc = 0; kc < 4; kc++) {
#pragma unroll
            for (int jp = 0; jp < 4; jp++) {
                uint32_t vh[4], vl[4];
                ldsm4t(vh[0], vh[1], vh[2], vh[3],
                       voffV + AOFF_VH + (uint32_t)(kc * 16 * ALD) + (uint32_t)(jp * 32));
                ldsm4t(vl[0], vl[1], vl[2], vl[3],
                       voffV + AOFF_VL + (uint32_t)(kc * 16 * ALD) + (uint32_t)(jp * 32));
                mma16816(O[jp * 2],     aPh[kc][0], aPh[kc][1], aPh[kc][2], aPh[kc][3], vh[0], vh[1]);
                mma16816(O[jp * 2],     aPh[kc][0], aPh[kc][1], aPh[kc][2], aPh[kc][3], vl[0], vl[1]);
                mma16816(O[jp * 2],     aPl[kc][0], aPl[kc][1], aPl[kc][2], aPl[kc][3], vh[0], vh[1]);
                mma16816(O[jp * 2 + 1], aPh[kc][0], aPh[kc][1], aPh[kc][2], aPh[kc][3], vh[2], vh[3]);
                mma16816(O[jp * 2 + 1], aPh[kc][0], aPh[kc][1], aPh[kc][2], aPh[kc][3], vl[2], vl[3]);
                mma16816(O[jp * 2 + 1], aPl[kc][0], aPl[kc][1], aPl[kc][2], aPl[kc][3], vh[2], vh[3]);
            }
        }
    }

    // ---- finalize: O /= l, write context in [B,S,D] layout ----
    const float inv0 = 1.0f / lstate[0];
    const float inv1 = 1.0f / lstate[1];
    float* Cb = C + (size_t)b * S_ * D_ + (size_t)h * DK_;
#pragma unroll
    for (int j = 0; j < 8; j++) {
        const int col = j * 8 + mcol;
        float2 o0 = { O[j][0] * inv0, O[j][1] * inv0 };
        float2 o1 = { O[j][2] * inv1, O[j][3] * inv1 };
        *(float2*)&Cb[(size_t)row0 * D_ + col]       = o0;
        *(float2*)&Cb[(size_t)(row0 + 8) * D_ + col] = o1;
    }
}

// ---------------------------------------------------------------------------
// Launch
// ---------------------------------------------------------------------------
extern "C" void kernel_launch(void* const* d_in, const int* in_sizes, int n_in,
                              void* d_out, int out_size)
{
    (void)in_sizes; (void)n_in; (void)out_size;
    const float* q    = (const float*)d_in[0];
    const float* k    = (const float*)d_in[1];
    const float* v    = (const float*)d_in[2];
    const int*   mask = (const int*)d_in[3];
    const float* w_q  = (const float*)d_in[4];
    const float* b_q  = (const float*)d_in[5];
    const float* w_k  = (const float*)d_in[6];
    const float* b_k  = (const float*)d_in[7];
    const float* w_v  = (const float*)d_in[8];
    const float* b_v  = (const float*)d_in[9];
    const float* w_o  = (const float*)d_in[10];
    const float* b_o  = (const float*)d_in[11];
    float* out = (float*)d_out;

    float *gQ, *gK, *gV, *gC;
    cudaGetSymbolAddress((void**)&gQ, g_Q);
    cudaGetSymbolAddress((void**)&gK, g_K);
    cudaGetSymbolAddress((void**)&gV, g_V);
    cudaGetSymbolAddress((void**)&gC, g_C);

    cudaFuncSetAttribute(attn_mma_kernel,
                         cudaFuncAttributeMaxDynamicSharedMemorySize,
                         ATTN_SMEM_BYTES);

    dim3 gblk(256);
    dim3 ggrid(D_ / BN, M_ / BM);     // (8, 32)

    gemm_mma_kernel<<<ggrid, gblk>>>(q, w_q, b_q, gQ);
    gemm_mma_kernel<<<ggrid, gblk>>>(k, w_k, b_k, gK);
    gemm_mma_kernel<<<ggrid, gblk>>>(v, w_v, b_v, gV);

    dim3 ablk(256);
    dim3 agrid(S_ / ATQ, B_ * H_);    // (16, 32)
    attn_mma_kernel<<<agrid, ablk, ATTN_SMEM_BYTES>>>(gQ, gK, gV, mask, gC);

    gemm_mma_kernel<<<ggrid, gblk>>>(gC, w_o, b_o, out);
}

// round 6
// speedup vs baseline: 3.3791x; 1.5336x over previous
#include <cuda_runtime.h>
#include <cuda_bf16.h>
#include <cstdint>

// Problem constants
#define B_  2
#define S_  2048
#define D_  1024
#define H_  16
#define DK_ 64
#define M_  (B_ * S_)   // 4096

// ---------------------------------------------------------------------------
// Scratch: Q/K/V stored pre-split as bf16 hi/lo; context fp32.
// ---------------------------------------------------------------------------
__device__ __nv_bfloat16 g_Qh[M_ * D_];
__device__ __nv_bfloat16 g_Ql[M_ * D_];
__device__ __nv_bfloat16 g_Kh[M_ * D_];
__device__ __nv_bfloat16 g_Kl[M_ * D_];
__device__ __nv_bfloat16 g_Vh[M_ * D_];
__device__ __nv_bfloat16 g_Vl[M_ * D_];
__device__ float g_C[M_ * D_];

__device__ __forceinline__ uint32_t smem_u32(const void* p) {
    uint32_t a;
    asm("{ .reg .u64 t; cvta.to.shared.u64 t, %1; cvt.u32.u64 %0, t; }"
        : "=r"(a) : "l"(p));
    return a;
}

__device__ __forceinline__ void mma16816(float* c,
                                         uint32_t a0, uint32_t a1, uint32_t a2, uint32_t a3,
                                         uint32_t b0, uint32_t b1) {
    asm volatile(
        "mma.sync.aligned.m16n8k16.row.col.f32.bf16.bf16.f32 "
        "{%0,%1,%2,%3}, {%4,%5,%6,%7}, {%8,%9}, {%0,%1,%2,%3};"
        : "+f"(c[0]), "+f"(c[1]), "+f"(c[2]), "+f"(c[3])
        : "r"(a0), "r"(a1), "r"(a2), "r"(a3), "r"(b0), "r"(b1));
}

__device__ __forceinline__ void ldsm4(uint32_t& r0, uint32_t& r1, uint32_t& r2, uint32_t& r3,
                                      uint32_t addr) {
    asm volatile("ldmatrix.sync.aligned.m8n8.x4.shared.b16 {%0,%1,%2,%3}, [%4];"
                 : "=r"(r0), "=r"(r1), "=r"(r2), "=r"(r3) : "r"(addr));
}

__device__ __forceinline__ void ldsm4t(uint32_t& r0, uint32_t& r1, uint32_t& r2, uint32_t& r3,
                                       uint32_t addr) {
    asm volatile("ldmatrix.sync.aligned.m8n8.x4.trans.shared.b16 {%0,%1,%2,%3}, [%4];"
                 : "=r"(r0), "=r"(r1), "=r"(r2), "=r"(r3) : "r"(addr));
}

union PackB4 { uint64_t u; __nv_bfloat16 b[4]; };

__device__ __forceinline__ void split4(float4 v, uint64_t& hi, uint64_t& lo) {
    PackB4 h, l;
    h.b[0] = __float2bfloat16_rn(v.x);
    h.b[1] = __float2bfloat16_rn(v.y);
    h.b[2] = __float2bfloat16_rn(v.z);
    h.b[3] = __float2bfloat16_rn(v.w);
    l.b[0] = __float2bfloat16_rn(v.x - __bfloat162float(h.b[0]));
    l.b[1] = __float2bfloat16_rn(v.y - __bfloat162float(h.b[1]));
    l.b[2] = __float2bfloat16_rn(v.z - __bfloat162float(h.b[2]));
    l.b[3] = __float2bfloat16_rn(v.w - __bfloat162float(h.b[3]));
    hi = h.u; lo = l.u;
}

__device__ __forceinline__ uint32_t packbf(float a, float b) {
    __nv_bfloat162 t = __floats2bfloat162_rn(a, b);
    return *(uint32_t*)&t;
}

// ===========================================================================
// Split-bf16 mma.sync GEMM+bias. Templated epilogue:
//   SPLIT=false: Yf = fp32 result (final projection -> d_out)
//   SPLIT=true : Yh/Yl = bf16 hi/lo of result (Q/K/V pre-split for attention)
// ===========================================================================
#define BM 128
#define BN 128
#define BK 32

template<bool SPLIT>
__global__ __launch_bounds__(256, 2) void gemm_mma_kernel(
    const float* __restrict__ X, const float* __restrict__ W,
    const float* __restrict__ bias, float* __restrict__ Yf,
    __nv_bfloat16* __restrict__ Yh, __nv_bfloat16* __restrict__ Yl)
{
    __shared__ __align__(128) __nv_bfloat16 sAh[BM * 40];
    __shared__ __align__(128) __nv_bfloat16 sAl[BM * 40];
    __shared__ __align__(128) __nv_bfloat16 sBh[BN * 40];
    __shared__ __align__(128) __nv_bfloat16 sBl[BN * 40];

    const int tid  = threadIdx.x;
    const int lane = tid & 31;
    const int wid  = tid >> 5;
    const int wm   = wid >> 2;
    const int wn   = wid & 3;
    const int m0 = blockIdx.y * BM;
    const int n0 = blockIdx.x * BN;

    const uint32_t bAh = smem_u32(sAh);
    const uint32_t bAl = smem_u32(sAl);
    const uint32_t bBh = smem_u32(sBh);
    const uint32_t bBl = smem_u32(sBl);

    const uint32_t aoff = (uint32_t)((lane & 15) * 80 + (lane >> 4) * 16);
    const uint32_t boff = (uint32_t)(((lane & 7) + ((lane >> 4) & 1) * 8) * 80 +
                                     (((lane >> 3) & 1) ? 16 : 0));

    const int lr = tid >> 3;
    const int lc = tid & 7;

    float C[4][4][4];
#pragma unroll
    for (int i = 0; i < 4; i++)
#pragma unroll
        for (int j = 0; j < 4; j++)
#pragma unroll
            for (int t = 0; t < 4; t++) C[i][j][t] = 0.0f;

    for (int k0 = 0; k0 < D_; k0 += BK) {
        __syncthreads();
#pragma unroll
        for (int it = 0; it < 4; it++) {
            const int r = lr + it * 32;
            uint64_t hi, lo;
            float4 xv = *(const float4*)&X[(size_t)(m0 + r) * D_ + k0 + lc * 4];
            split4(xv, hi, lo);
            *(uint64_t*)((char*)sAh + r * 80 + lc * 8) = hi;
            *(uint64_t*)((char*)sAl + r * 80 + lc * 8) = lo;
            float4 wv = *(const float4*)&W[(size_t)(n0 + r) * D_ + k0 + lc * 4];
            split4(wv, hi, lo);
            *(uint64_t*)((char*)sBh + r * 80 + lc * 8) = hi;
            *(uint64_t*)((char*)sBl + r * 80 + lc * 8) = lo;
        }
        __syncthreads();

#pragma unroll
        for (int ks = 0; ks < 2; ks++) {
            const uint32_t kbyte = (uint32_t)(ks * 32);
            uint32_t bh[2][4], bl[2][4];
#pragma unroll
            for (int p = 0; p < 2; p++) {
                ldsm4(bh[p][0], bh[p][1], bh[p][2], bh[p][3],
                      bBh + (uint32_t)((wn * 32 + p * 16) * 80) + kbyte + boff);
                ldsm4(bl[p][0], bl[p][1], bl[p][2], bl[p][3],
                      bBl + (uint32_t)((wn * 32 + p * 16) * 80) + kbyte + boff);
            }
            {
                uint32_t a[4][4];
#pragma unroll
                for (int i = 0; i < 4; i++)
                    ldsm4(a[i][0], a[i][1], a[i][2], a[i][3],
                          bAh + (uint32_t)((wm * 64 + i * 16) * 80) + kbyte + aoff);
#pragma unroll
                for (int i = 0; i < 4; i++)
#pragma unroll
                    for (int j = 0; j < 4; j++) {
                        mma16816(C[i][j], a[i][0], a[i][1], a[i][2], a[i][3],
                                 bh[j >> 1][(j & 1) * 2], bh[j >> 1][(j & 1) * 2 + 1]);
                        mma16816(C[i][j], a[i][0], a[i][1], a[i][2], a[i][3],
                                 bl[j >> 1][(j & 1) * 2], bl[j >> 1][(j & 1) * 2 + 1]);
                    }
            }
            {
                uint32_t a[4][4];
#pragma unroll
                for (int i = 0; i < 4; i++)
                    ldsm4(a[i][0], a[i][1], a[i][2], a[i][3],
                          bAl + (uint32_t)((wm * 64 + i * 16) * 80) + kbyte + aoff);
#pragma unroll
                for (int i = 0; i < 4; i++)
#pragma unroll
                    for (int j = 0; j < 4; j++)
                        mma16816(C[i][j], a[i][0], a[i][1], a[i][2], a[i][3],
                                 bh[j >> 1][(j & 1) * 2], bh[j >> 1][(j & 1) * 2 + 1]);
            }
        }
    }

    const int qr = lane >> 2;
    const int qc = (lane & 3) * 2;
#pragma unroll
    for (int i = 0; i < 4; i++) {
        const int row0 = m0 + wm * 64 + i * 16 + qr;
#pragma unroll
        for (int j = 0; j < 4; j++) {
            const int col = n0 + wn * 32 + j * 8 + qc;
            const float b0v = bias[col], b1v = bias[col + 1];
            float v0 = C[i][j][0] + b0v, v1 = C[i][j][1] + b1v;
            float v2 = C[i][j][2] + b0v, v3 = C[i][j][3] + b1v;
            if (SPLIT) {
                __nv_bfloat16 h0 = __float2bfloat16_rn(v0);
                __nv_bfloat16 h1 = __float2bfloat16_rn(v1);
                __nv_bfloat16 h2 = __float2bfloat16_rn(v2);
                __nv_bfloat16 h3 = __float2bfloat16_rn(v3);
                __nv_bfloat162 hp0; hp0.x = h0; hp0.y = h1;
                __nv_bfloat162 hp1; hp1.x = h2; hp1.y = h3;
                *(uint32_t*)&Yh[(size_t)row0 * D_ + col]       = *(uint32_t*)&hp0;
                *(uint32_t*)&Yh[(size_t)(row0 + 8) * D_ + col] = *(uint32_t*)&hp1;
                *(uint32_t*)&Yl[(size_t)row0 * D_ + col] =
                    packbf(v0 - __bfloat162float(h0), v1 - __bfloat162float(h1));
                *(uint32_t*)&Yl[(size_t)(row0 + 8) * D_ + col] =
                    packbf(v2 - __bfloat162float(h2), v3 - __bfloat162float(h3));
            } else {
                float2 o0 = { v0, v1 };
                float2 o1 = { v2, v3 };
                *(float2*)&Yf[(size_t)row0 * D_ + col]       = o0;
                *(float2*)&Yf[(size_t)(row0 + 8) * D_ + col] = o1;
            }
        }
    }
}

// ===========================================================================
// Flash attention, split-bf16 mma.sync, inputs pre-split by projection GEMMs.
// CTA: 128 query rows x one (b,h). 8 warps. K-tiles of 64.
// ===========================================================================
#define ATQ 128
#define ATK 64
#define ALD 144   // bytes per smem row

#define AOFF_QH 0
#define AOFF_QL (AOFF_QH + ATQ * ALD)
#define AOFF_KH (AOFF_QL + ATQ * ALD)
#define AOFF_KL (AOFF_KH + ATK * ALD)
#define AOFF_VH (AOFF_KL + ATK * ALD)
#define AOFF_VL (AOFF_VH + ATK * ALD)
#define ATTN_SMEM_BYTES (AOFF_VL + ATK * ALD)  // 73728

__global__ __launch_bounds__(256) void attn_mma_kernel(
    const __nv_bfloat16* __restrict__ Qh, const __nv_bfloat16* __restrict__ Ql,
    const __nv_bfloat16* __restrict__ Kh, const __nv_bfloat16* __restrict__ Kl,
    const __nv_bfloat16* __restrict__ Vh, const __nv_bfloat16* __restrict__ Vl,
    const int* __restrict__ mask, float* __restrict__ C)
{
    extern __shared__ __align__(128) char smem[];
    const uint32_t sb = smem_u32(smem);

    const int tid  = threadIdx.x;
    const int lane = tid & 31;
    const int wid  = tid >> 5;
    const int bh = blockIdx.y;
    const int b  = bh >> 4;
    const int h  = bh & 15;
    const int q0 = blockIdx.x * ATQ;

    const size_t base = (size_t)b * S_ * D_ + (size_t)h * DK_;
    const __nv_bfloat16* Qhb = Qh + base;
    const __nv_bfloat16* Qlb = Ql + base;
    const __nv_bfloat16* Khb = Kh + base;
    const __nv_bfloat16* Klb = Kl + base;
    const __nv_bfloat16* Vhb = Vh + base;
    const __nv_bfloat16* Vlb = Vl + base;
    const int* Mb = mask + (size_t)b * S_ * S_;

    // ---- load Q tile (128 x 64 bf16 hi/lo): pure uint4 copies ----
    {
        const int r = tid >> 1;          // 0..127
        const int c = tid & 1;           // two 16B chunks? need 8 per row
        // 128 rows * 8 uint4 per row per array = 1024 uint4; 256 thr -> 4 iters
#pragma unroll
        for (int i = 0; i < 4; i++) {
            const int idx = tid + i * 256;
            const int rr = idx >> 3;
            const int cc = idx & 7;
            *(uint4*)(smem + AOFF_QH + rr * ALD + cc * 16) =
                *(const uint4*)&Qhb[(size_t)(q0 + rr) * D_ + cc * 8];
            *(uint4*)(smem + AOFF_QL + rr * ALD + cc * 16) =
                *(const uint4*)&Qlb[(size_t)(q0 + rr) * D_ + cc * 8];
        }
        (void)r; (void)c;
    }

    const uint32_t aoffQ = sb + (uint32_t)((wid * 16 + (lane & 15)) * ALD + (lane >> 4) * 16);
    const uint32_t boffK = sb + (uint32_t)(((lane & 7) + ((lane >> 4) & 1) * 8) * ALD +
                                           ((lane >> 3) & 1) * 16);
    const uint32_t voffV = sb + (uint32_t)((((lane >> 3) & 1) * 8 + (lane & 7)) * ALD +
                                           ((lane >> 4) & 1) * 16);

    float mstate[2] = { -1e30f, -1e30f };
    float lstate[2] = { 0.0f, 0.0f };
    float O[8][4];
#pragma unroll
    for (int j = 0; j < 8; j++)
#pragma unroll
        for (int t = 0; t < 4; t++) O[j][t] = 0.0f;

    const int row0 = q0 + wid * 16 + (lane >> 2);
    const int mcol = (lane & 3) * 2;
    const int* mrow0 = Mb + (size_t)row0 * S_;
    const int* mrow1 = Mb + (size_t)(row0 + 8) * S_;

    for (int k0 = 0; k0 < S_; k0 += ATK) {
        __syncthreads();
        // ---- load K,V tiles (64 x 64 bf16 hi/lo): uint4 copies ----
        // 64 rows * 8 uint4 per array = 512; 256 thr -> 2 iters x 4 arrays
#pragma unroll
        for (int i = 0; i < 2; i++) {
            const int idx = tid + i * 256;
            const int rr = idx >> 3;
            const int cc = idx & 7;
            const size_t g = (size_t)(k0 + rr) * D_ + cc * 8;
            *(uint4*)(smem + AOFF_KH + rr * ALD + cc * 16) = *(const uint4*)&Khb[g];
            *(uint4*)(smem + AOFF_KL + rr * ALD + cc * 16) = *(const uint4*)&Klb[g];
            *(uint4*)(smem + AOFF_VH + rr * ALD + cc * 16) = *(const uint4*)&Vhb[g];
            *(uint4*)(smem + AOFF_VL + rr * ALD + cc * 16) = *(const uint4*)&Vlb[g];
        }
        __syncthreads();

        // ---- S = Q K^T (split compensated) ----
        float Sf[8][4];
#pragma unroll
        for (int j = 0; j < 8; j++)
#pragma unroll
            for (int t = 0; t < 4; t++) Sf[j][t] = 0.0f;

#pragma unroll
        for (int kc = 0; kc < 4; kc++) {
            const uint32_t kb = (uint32_t)(kc * 32);
            uint32_t ah[4], al[4];
            ldsm4(ah[0], ah[1], ah[2], ah[3], aoffQ + AOFF_QH + kb);
            ldsm4(al[0], al[1], al[2], al[3], aoffQ + AOFF_QL + kb);
#pragma unroll
            for (int jp = 0; jp < 4; jp++) {
                uint32_t kh[4], kl[4];
                ldsm4(kh[0], kh[1], kh[2], kh[3],
                      boffK + AOFF_KH + (uint32_t)(jp * 16 * ALD) + kb);
                ldsm4(kl[0], kl[1], kl[2], kl[3],
                      boffK + AOFF_KL + (uint32_t)(jp * 16 * ALD) + kb);
                mma16816(Sf[jp * 2],     ah[0], ah[1], ah[2], ah[3], kh[0], kh[1]);
                mma16816(Sf[jp * 2],     ah[0], ah[1], ah[2], ah[3], kl[0], kl[1]);
                mma16816(Sf[jp * 2],     al[0], al[1], al[2], al[3], kh[0], kh[1]);
                mma16816(Sf[jp * 2 + 1], ah[0], ah[1], ah[2], ah[3], kh[2], kh[3]);
                mma16816(Sf[jp * 2 + 1], ah[0], ah[1], ah[2], ah[3], kl[2], kl[3]);
                mma16816(Sf[jp * 2 + 1], al[0], al[1], al[2], al[3], kh[2], kh[3]);
            }
        }

        // ---- scale + mask ----
#pragma unroll
        for (int j = 0; j < 8; j++) {
            int2 mv0 = *(const int2*)&mrow0[k0 + j * 8 + mcol];
            int2 mv1 = *(const int2*)&mrow1[k0 + j * 8 + mcol];
            Sf[j][0] = (mv0.x == 0) ? -1e9f : Sf[j][0] * 0.125f;
            Sf[j][1] = (mv0.y == 0) ? -1e9f : Sf[j][1] * 0.125f;
            Sf[j][2] = (mv1.x == 0) ? -1e9f : Sf[j][2] * 0.125f;
            Sf[j][3] = (mv1.y == 0) ? -1e9f : Sf[j][3] * 0.125f;
        }

        // ---- online softmax ----
        float corr[2];
#pragma unroll
        for (int rr = 0; rr < 2; rr++) {
            float mx = -1e30f;
#pragma unroll
            for (int j = 0; j < 8; j++)
                mx = fmaxf(mx, fmaxf(Sf[j][rr * 2], Sf[j][rr * 2 + 1]));
            mx = fmaxf(mx, __shfl_xor_sync(0xFFFFFFFF, mx, 1));
            mx = fmaxf(mx, __shfl_xor_sync(0xFFFFFFFF, mx, 2));
            float mnew = fmaxf(mstate[rr], mx);
            corr[rr] = __expf(mstate[rr] - mnew);
            float sum = 0.0f;
#pragma unroll
            for (int j = 0; j < 8; j++) {
                float p0 = __expf(Sf[j][rr * 2]     - mnew);
                float p1 = __expf(Sf[j][rr * 2 + 1] - mnew);
                Sf[j][rr * 2] = p0; Sf[j][rr * 2 + 1] = p1;
                sum += p0 + p1;
            }
            sum += __shfl_xor_sync(0xFFFFFFFF, sum, 1);
            sum += __shfl_xor_sync(0xFFFFFFFF, sum, 2);
            lstate[rr] = lstate[rr] * corr[rr] + sum;
            mstate[rr] = mnew;
        }

#pragma unroll
        for (int j = 0; j < 8; j++) {
            O[j][0] *= corr[0]; O[j][1] *= corr[0];
            O[j][2] *= corr[1]; O[j][3] *= corr[1];
        }

        // ---- pack P (hi/lo split) ----
        uint32_t aPh[4][4], aPl[4][4];
#pragma unroll
        for (int kc = 0; kc < 4; kc++) {
#pragma unroll
            for (int half = 0; half < 2; half++) {
                const int j = kc * 2 + half;
#pragma unroll
                for (int rr = 0; rr < 2; rr++) {
                    float p0 = Sf[j][rr * 2], p1 = Sf[j][rr * 2 + 1];
                    __nv_bfloat16 h0 = __float2bfloat16_rn(p0);
                    __nv_bfloat16 h1 = __float2bfloat16_rn(p1);
                    __nv_bfloat162 hp; hp.x = h0; hp.y = h1;
                    aPh[kc][half * 2 + rr] = *(uint32_t*)&hp;
                    aPl[kc][half * 2 + rr] =
                        packbf(p0 - __bfloat162float(h0), p1 - __bfloat162float(h1));
                }
            }
        }

        // ---- O += P V (split compensated) ----
#pragma unroll
        for (int kc = 0; kc < 4; kc++) {
#pragma unroll
            for (int jp = 0; jp < 4; jp++) {
                uint32_t vh[4], vl[4];
                ldsm4t(vh[0], vh[1], vh[2], vh[3],
                       voffV + AOFF_VH + (uint32_t)(kc * 16 * ALD) + (uint32_t)(jp * 32));
                ldsm4t(vl[0], vl[1], vl[2], vl[3],
                       voffV + AOFF_VL + (uint32_t)(kc * 16 * ALD) + (uint32_t)(jp * 32));
                mma16816(O[jp * 2],     aPh[kc][0], aPh[kc][1], aPh[kc][2], aPh[kc][3], vh[0], vh[1]);
                mma16816(O[jp * 2],     aPh[kc][0], aPh[kc][1], aPh[kc][2], aPh[kc][3], vl[0], vl[1]);
                mma16816(O[jp * 2],     aPl[kc][0], aPl[kc][1], aPl[kc][2], aPl[kc][3], vh[0], vh[1]);
                mma16816(O[jp * 2 + 1], aPh[kc][0], aPh[kc][1], aPh[kc][2], aPh[kc][3], vh[2], vh[3]);
                mma16816(O[jp * 2 + 1], aPh[kc][0], aPh[kc][1], aPh[kc][2], aPh[kc][3], vl[2], vl[3]);
                mma16816(O[jp * 2 + 1], aPl[kc][0], aPl[kc][1], aPl[kc][2], aPl[kc][3], vh[2], vh[3]);
            }
        }
    }

    // ---- finalize ----
    const float inv0 = 1.0f / lstate[0];
    const float inv1 = 1.0f / lstate[1];
    float* Cb = C + (size_t)b * S_ * D_ + (size_t)h * DK_;
#pragma unroll
    for (int j = 0; j < 8; j++) {
        const int col = j * 8 + mcol;
        float2 o0 = { O[j][0] * inv0, O[j][1] * inv0 };
        float2 o1 = { O[j][2] * inv1, O[j][3] * inv1 };
        *(float2*)&Cb[(size_t)row0 * D_ + col]       = o0;
        *(float2*)&Cb[(size_t)(row0 + 8) * D_ + col] = o1;
    }
}

// ---------------------------------------------------------------------------
// Launch
// ---------------------------------------------------------------------------
extern "C" void kernel_launch(void* const* d_in, const int* in_sizes, int n_in,
                              void* d_out, int out_size)
{
    (void)in_sizes; (void)n_in; (void)out_size;
    const float* q    = (const float*)d_in[0];
    const float* k    = (const float*)d_in[1];
    const float* v    = (const float*)d_in[2];
    const int*   mask = (const int*)d_in[3];
    const float* w_q  = (const float*)d_in[4];
    const float* b_q  = (const float*)d_in[5];
    const float* w_k  = (const float*)d_in[6];
    const float* b_k  = (const float*)d_in[7];
    const float* w_v  = (const float*)d_in[8];
    const float* b_v  = (const float*)d_in[9];
    const float* w_o  = (const float*)d_in[10];
    const float* b_o  = (const float*)d_in[11];
    float* out = (float*)d_out;

    __nv_bfloat16 *gQh, *gQl, *gKh, *gKl, *gVh, *gVl;
    float *gC;
    cudaGetSymbolAddress((void**)&gQh, g_Qh);
    cudaGetSymbolAddress((void**)&gQl, g_Ql);
    cudaGetSymbolAddress((void**)&gKh, g_Kh);
    cudaGetSymbolAddress((void**)&gKl, g_Kl);
    cudaGetSymbolAddress((void**)&gVh, g_Vh);
    cudaGetSymbolAddress((void**)&gVl, g_Vl);
    cudaGetSymbolAddress((void**)&gC,  g_C);

    cudaFuncSetAttribute(attn_mma_kernel,
                         cudaFuncAttributeMaxDynamicSharedMemorySize,
                         ATTN_SMEM_BYTES);

    dim3 gblk(256);
    dim3 ggrid(D_ / BN, M_ / BM);     // (8, 32)

    gemm_mma_kernel<true><<<ggrid, gblk>>>(q, w_q, b_q, nullptr, gQh, gQl);
    gemm_mma_kernel<true><<<ggrid, gblk>>>(k, w_k, b_k, nullptr, gKh, gKl);
    gemm_mma_kernel<true><<<ggrid, gblk>>>(v, w_v, b_v, nullptr, gVh, gVl);

    dim3 ablk(256);
    dim3 agrid(S_ / ATQ, B_ * H_);    // (16, 32)
    attn_mma_kernel<<<agrid, ablk, ATTN_SMEM_BYTES>>>(
        gQh, gQl, gKh, gKl, gVh, gVl, mask, gC);

    gemm_mma_kernel<false><<<ggrid, gblk>>>(gC, w_o, b_o, out, nullptr, nullptr);
}

// round 7
// speedup vs baseline: 3.4053x; 1.0077x over previous
#include <cuda_runtime.h>
#include <cuda_bf16.h>
#include <cstdint>

// Problem constants
#define B_  2
#define S_  2048
#define D_  1024
#define H_  16
#define DK_ 64
#define M_  (B_ * S_)   // 4096

// ---------------------------------------------------------------------------
// Scratch: Q/K/V and context stored pre-split as bf16 hi/lo.
// ---------------------------------------------------------------------------
__device__ __nv_bfloat16 g_Qh[M_ * D_];
__device__ __nv_bfloat16 g_Ql[M_ * D_];
__device__ __nv_bfloat16 g_Kh[M_ * D_];
__device__ __nv_bfloat16 g_Kl[M_ * D_];
__device__ __nv_bfloat16 g_Vh[M_ * D_];
__device__ __nv_bfloat16 g_Vl[M_ * D_];
__device__ __nv_bfloat16 g_Ch[M_ * D_];
__device__ __nv_bfloat16 g_Cl[M_ * D_];

__device__ __forceinline__ uint32_t smem_u32(const void* p) {
    uint32_t a;
    asm("{ .reg .u64 t; cvta.to.shared.u64 t, %1; cvt.u32.u64 %0, t; }"
        : "=r"(a) : "l"(p));
    return a;
}

__device__ __forceinline__ void mma16816(float* c,
                                         uint32_t a0, uint32_t a1, uint32_t a2, uint32_t a3,
                                         uint32_t b0, uint32_t b1) {
    asm volatile(
        "mma.sync.aligned.m16n8k16.row.col.f32.bf16.bf16.f32 "
        "{%0,%1,%2,%3}, {%4,%5,%6,%7}, {%8,%9}, {%0,%1,%2,%3};"
        : "+f"(c[0]), "+f"(c[1]), "+f"(c[2]), "+f"(c[3])
        : "r"(a0), "r"(a1), "r"(a2), "r"(a3), "r"(b0), "r"(b1));
}

__device__ __forceinline__ void ldsm4(uint32_t& r0, uint32_t& r1, uint32_t& r2, uint32_t& r3,
                                      uint32_t addr) {
    asm volatile("ldmatrix.sync.aligned.m8n8.x4.shared.b16 {%0,%1,%2,%3}, [%4];"
                 : "=r"(r0), "=r"(r1), "=r"(r2), "=r"(r3) : "r"(addr));
}

__device__ __forceinline__ void ldsm4t(uint32_t& r0, uint32_t& r1, uint32_t& r2, uint32_t& r3,
                                       uint32_t addr) {
    asm volatile("ldmatrix.sync.aligned.m8n8.x4.trans.shared.b16 {%0,%1,%2,%3}, [%4];"
                 : "=r"(r0), "=r"(r1), "=r"(r2), "=r"(r3) : "r"(addr));
}

#define CPASYNC16(saddr, gptr) \
    asm volatile("cp.async.cg.shared.global [%0], [%1], 16;" \
                 :: "r"((uint32_t)(saddr)), "l"(gptr))
#define CPCOMMIT() asm volatile("cp.async.commit_group;" ::: "memory")
#define CPWAIT1()  asm volatile("cp.async.wait_group 1;" ::: "memory")
#define CPWAIT0()  asm volatile("cp.async.wait_group 0;" ::: "memory")

union PackB4 { uint64_t u; __nv_bfloat16 b[4]; };

__device__ __forceinline__ void split4(float4 v, uint64_t& hi, uint64_t& lo) {
    PackB4 h, l;
    h.b[0] = __float2bfloat16_rn(v.x);
    h.b[1] = __float2bfloat16_rn(v.y);
    h.b[2] = __float2bfloat16_rn(v.z);
    h.b[3] = __float2bfloat16_rn(v.w);
    l.b[0] = __float2bfloat16_rn(v.x - __bfloat162float(h.b[0]));
    l.b[1] = __float2bfloat16_rn(v.y - __bfloat162float(h.b[1]));
    l.b[2] = __float2bfloat16_rn(v.z - __bfloat162float(h.b[2]));
    l.b[3] = __float2bfloat16_rn(v.w - __bfloat162float(h.b[3]));
    hi = h.u; lo = l.u;
}

__device__ __forceinline__ uint32_t packbf(float a, float b) {
    __nv_bfloat162 t = __floats2bfloat162_rn(a, b);
    return *(uint32_t*)&t;
}

// ===========================================================================
// Split-bf16 mma.sync GEMM+bias.
// MODE 0: fp32 X in, bf16 hi/lo out (Q/K/V projections; batched over z)
// MODE 1: pre-split bf16 A in (Ah/Al), fp32 out (final projection)
// ===========================================================================
#define BM 128
#define BN 128
#define BK 32

template<int MODE>
__global__ __launch_bounds__(256, 2) void gemm_mma_kernel(
    const float* __restrict__ X0, const float* __restrict__ X1, const float* __restrict__ X2,
    const __nv_bfloat16* __restrict__ Ah, const __nv_bfloat16* __restrict__ Al,
    const float* __restrict__ W0, const float* __restrict__ W1, const float* __restrict__ W2,
    const float* __restrict__ bias0, const float* __restrict__ bias1, const float* __restrict__ bias2,
    float* __restrict__ Yf,
    __nv_bfloat16* __restrict__ Yh0, __nv_bfloat16* __restrict__ Yh1, __nv_bfloat16* __restrict__ Yh2,
    __nv_bfloat16* __restrict__ Yl0, __nv_bfloat16* __restrict__ Yl1, __nv_bfloat16* __restrict__ Yl2)
{
    __shared__ __align__(128) __nv_bfloat16 sAh[BM * 40];
    __shared__ __align__(128) __nv_bfloat16 sAl[BM * 40];
    __shared__ __align__(128) __nv_bfloat16 sBh[BN * 40];
    __shared__ __align__(128) __nv_bfloat16 sBl[BN * 40];

    const int tid  = threadIdx.x;
    const int lane = tid & 31;
    const int wid  = tid >> 5;
    const int wm   = wid >> 2;
    const int wn   = wid & 3;
    const int m0 = blockIdx.y * BM;
    const int n0 = blockIdx.x * BN;
    const int z  = blockIdx.z;

    const float* X = (z == 0) ? X0 : (z == 1) ? X1 : X2;
    const float* W = (z == 0) ? W0 : (z == 1) ? W1 : W2;
    const float* bias = (z == 0) ? bias0 : (z == 1) ? bias1 : bias2;
    __nv_bfloat16* Yh = (z == 0) ? Yh0 : (z == 1) ? Yh1 : Yh2;
    __nv_bfloat16* Yl = (z == 0) ? Yl0 : (z == 1) ? Yl1 : Yl2;

    const uint32_t bAh = smem_u32(sAh);
    const uint32_t bAl = smem_u32(sAl);
    const uint32_t bBh = smem_u32(sBh);
    const uint32_t bBl = smem_u32(sBl);

    const uint32_t aoff = (uint32_t)((lane & 15) * 80 + (lane >> 4) * 16);
    const uint32_t boff = (uint32_t)(((lane & 7) + ((lane >> 4) & 1) * 8) * 80 +
                                     (((lane >> 3) & 1) ? 16 : 0));

    const int lr = tid >> 3;
    const int lc = tid & 7;

    float C[4][4][4];
#pragma unroll
    for (int i = 0; i < 4; i++)
#pragma unroll
        for (int j = 0; j < 4; j++)
#pragma unroll
            for (int t = 0; t < 4; t++) C[i][j][t] = 0.0f;

    for (int k0 = 0; k0 < D_; k0 += BK) {
        __syncthreads();
        if (MODE == 0) {
#pragma unroll
            for (int it = 0; it < 4; it++) {
                const int r = lr + it * 32;
                uint64_t hi, lo;
                float4 xv = *(const float4*)&X[(size_t)(m0 + r) * D_ + k0 + lc * 4];
                split4(xv, hi, lo);
                *(uint64_t*)((char*)sAh + r * 80 + lc * 8) = hi;
                *(uint64_t*)((char*)sAl + r * 80 + lc * 8) = lo;
            }
        } else {
            // pre-split A: 128 rows x 32 bf16 cols -> 4 uint4 per row per array
#pragma unroll
            for (int i = 0; i < 2; i++) {
                const int idx = tid + i * 256;
                const int rr = idx >> 2;         // 0..127
                const int cc = idx & 3;          // 0..3 (8 bf16 each)
                const size_t g = (size_t)(m0 + rr) * D_ + k0 + cc * 8;
                *(uint4*)((char*)sAh + rr * 80 + cc * 16) = *(const uint4*)&Ah[g];
                *(uint4*)((char*)sAl + rr * 80 + cc * 16) = *(const uint4*)&Al[g];
            }
        }
#pragma unroll
        for (int it = 0; it < 4; it++) {
            const int r = lr + it * 32;
            uint64_t hi, lo;
            float4 wv = *(const float4*)&W[(size_t)(n0 + r) * D_ + k0 + lc * 4];
            split4(wv, hi, lo);
            *(uint64_t*)((char*)sBh + r * 80 + lc * 8) = hi;
            *(uint64_t*)((char*)sBl + r * 80 + lc * 8) = lo;
        }
        __syncthreads();

#pragma unroll
        for (int ks = 0; ks < 2; ks++) {
            const uint32_t kbyte = (uint32_t)(ks * 32);
            uint32_t bh[2][4], bl[2][4];
#pragma unroll
            for (int p = 0; p < 2; p++) {
                ldsm4(bh[p][0], bh[p][1], bh[p][2], bh[p][3],
                      bBh + (uint32_t)((wn * 32 + p * 16) * 80) + kbyte + boff);
                ldsm4(bl[p][0], bl[p][1], bl[p][2], bl[p][3],
                      bBl + (uint32_t)((wn * 32 + p * 16) * 80) + kbyte + boff);
            }
            {
                uint32_t a[4][4];
#pragma unroll
                for (int i = 0; i < 4; i++)
                    ldsm4(a[i][0], a[i][1], a[i][2], a[i][3],
                          bAh + (uint32_t)((wm * 64 + i * 16) * 80) + kbyte + aoff);
#pragma unroll
                for (int i = 0; i < 4; i++)
#pragma unroll
                    for (int j = 0; j < 4; j++) {
                        mma16816(C[i][j], a[i][0], a[i][1], a[i][2], a[i][3],
                                 bh[j >> 1][(j & 1) * 2], bh[j >> 1][(j & 1) * 2 + 1]);
                        mma16816(C[i][j], a[i][0], a[i][1], a[i][2], a[i][3],
                                 bl[j >> 1][(j & 1) * 2], bl[j >> 1][(j & 1) * 2 + 1]);
                    }
            }
            {
                uint32_t a[4][4];
#pragma unroll
                for (int i = 0; i < 4; i++)
                    ldsm4(a[i][0], a[i][1], a[i][2], a[i][3],
                          bAl + (uint32_t)((wm * 64 + i * 16) * 80) + kbyte + aoff);
#pragma unroll
                for (int i = 0; i < 4; i++)
#pragma unroll
                    for (int j = 0; j < 4; j++)
                        mma16816(C[i][j], a[i][0], a[i][1], a[i][2], a[i][3],
                                 bh[j >> 1][(j & 1) * 2], bh[j >> 1][(j & 1) * 2 + 1]);
            }
        }
    }

    const int qr = lane >> 2;
    const int qc = (lane & 3) * 2;
#pragma unroll
    for (int i = 0; i < 4; i++) {
        const int row0 = m0 + wm * 64 + i * 16 + qr;
#pragma unroll
        for (int j = 0; j < 4; j++) {
            const int col = n0 + wn * 32 + j * 8 + qc;
            const float b0v = bias[col], b1v = bias[col + 1];
            float v0 = C[i][j][0] + b0v, v1 = C[i][j][1] + b1v;
            float v2 = C[i][j][2] + b0v, v3 = C[i][j][3] + b1v;
            if (MODE == 0) {
                __nv_bfloat16 h0 = __float2bfloat16_rn(v0);
                __nv_bfloat16 h1 = __float2bfloat16_rn(v1);
                __nv_bfloat16 h2 = __float2bfloat16_rn(v2);
                __nv_bfloat16 h3 = __float2bfloat16_rn(v3);
                __nv_bfloat162 hp0; hp0.x = h0; hp0.y = h1;
                __nv_bfloat162 hp1; hp1.x = h2; hp1.y = h3;
                *(uint32_t*)&Yh[(size_t)row0 * D_ + col]       = *(uint32_t*)&hp0;
                *(uint32_t*)&Yh[(size_t)(row0 + 8) * D_ + col] = *(uint32_t*)&hp1;
                *(uint32_t*)&Yl[(size_t)row0 * D_ + col] =
                    packbf(v0 - __bfloat162float(h0), v1 - __bfloat162float(h1));
                *(uint32_t*)&Yl[(size_t)(row0 + 8) * D_ + col] =
                    packbf(v2 - __bfloat162float(h2), v3 - __bfloat162float(h3));
            } else {
                float2 o0 = { v0, v1 };
                float2 o1 = { v2, v3 };
                *(float2*)&Yf[(size_t)row0 * D_ + col]       = o0;
                *(float2*)&Yf[(size_t)(row0 + 8) * D_ + col] = o1;
            }
        }
    }
}

// ===========================================================================
// Flash attention, split-bf16 mma.sync, cp.async double-buffered K/V.
// CTA: 128 query rows x one (b,h). 8 warps. K-tiles of 64.
// Writes pre-split bf16 hi/lo context.
// ===========================================================================
#define ATQ 128
#define ATK 64
#define ALD 144   // bytes per smem row

#define AOFF_QH 0
#define AOFF_QL (AOFF_QH + ATQ * ALD)          // 18432
#define AOFF_BUF (AOFF_QL + ATQ * ALD)         // 36864
#define BUF_BYTES (4 * ATK * ALD)              // 36864 (KH,KL,VH,VL)
#define BKH 0
#define BKL (ATK * ALD)
#define BVH (2 * ATK * ALD)
#define BVL (3 * ATK * ALD)
#define ATTN_SMEM_BYTES (AOFF_BUF + 2 * BUF_BYTES)   // 110592

__global__ __launch_bounds__(256) void attn_mma_kernel(
    const __nv_bfloat16* __restrict__ Qh, const __nv_bfloat16* __restrict__ Ql,
    const __nv_bfloat16* __restrict__ Kh, const __nv_bfloat16* __restrict__ Kl,
    const __nv_bfloat16* __restrict__ Vh, const __nv_bfloat16* __restrict__ Vl,
    const int* __restrict__ mask,
    __nv_bfloat16* __restrict__ Ch, __nv_bfloat16* __restrict__ Cl)
{
    extern __shared__ __align__(128) char smem[];
    const uint32_t sb = smem_u32(smem);

    const int tid  = threadIdx.x;
    const int lane = tid & 31;
    const int wid  = tid >> 5;
    const int bh = blockIdx.y;
    const int b  = bh >> 4;
    const int h  = bh & 15;
    const int q0 = blockIdx.x * ATQ;

    const size_t base = (size_t)b * S_ * D_ + (size_t)h * DK_;
    const __nv_bfloat16* Qhb = Qh + base;
    const __nv_bfloat16* Qlb = Ql + base;
    const __nv_bfloat16* Khb = Kh + base;
    const __nv_bfloat16* Klb = Kl + base;
    const __nv_bfloat16* Vhb = Vh + base;
    const __nv_bfloat16* Vlb = Vl + base;
    const int* Mb = mask + (size_t)b * S_ * S_;

    // K/V tile loader lane mapping (cp.async, 8 x 16B per thread per tile)
    const int krr = tid >> 3;          // 0..31 (x2 -> 64 rows)
    const int kcc = tid & 7;           // 16B column

    // ---- prologue: issue tile 0 into buf 0, and load Q via plain copies ----
    {
#pragma unroll
        for (int i = 0; i < 2; i++) {
            const int rr = krr + i * 32;
            const size_t g = (size_t)rr * D_ + kcc * 8;
            const uint32_t s = sb + AOFF_BUF + rr * ALD + kcc * 16;
            CPASYNC16(s + BKH, &Khb[g]);
            CPASYNC16(s + BKL, &Klb[g]);
            CPASYNC16(s + BVH, &Vhb[g]);
            CPASYNC16(s + BVL, &Vlb[g]);
        }
        CPCOMMIT();
#pragma unroll
        for (int i = 0; i < 4; i++) {
            const int idx = tid + i * 256;
            const int rr = idx >> 3;
            const int cc = idx & 7;
            *(uint4*)(smem + AOFF_QH + rr * ALD + cc * 16) =
                *(const uint4*)&Qhb[(size_t)(q0 + rr) * D_ + cc * 8];
            *(uint4*)(smem + AOFF_QL + rr * ALD + cc * 16) =
                *(const uint4*)&Qlb[(size_t)(q0 + rr) * D_ + cc * 8];
        }
    }

    const uint32_t aoffQ = sb + (uint32_t)((wid * 16 + (lane & 15)) * ALD + (lane >> 4) * 16);
    const uint32_t loffK = (uint32_t)(((lane & 7) + ((lane >> 4) & 1) * 8) * ALD +
                                      ((lane >> 3) & 1) * 16);
    const uint32_t loffV = (uint32_t)((((lane >> 3) & 1) * 8 + (lane & 7)) * ALD +
                                      ((lane >> 4) & 1) * 16);

    float mstate[2] = { -1e30f, -1e30f };
    float lstate[2] = { 0.0f, 0.0f };
    float O[8][4];
#pragma unroll
    for (int j = 0; j < 8; j++)
#pragma unroll
        for (int t = 0; t < 4; t++) O[j][t] = 0.0f;

    const int row0 = q0 + wid * 16 + (lane >> 2);
    const int mcol = (lane & 3) * 2;
    const int* mrow0 = Mb + (size_t)row0 * S_;
    const int* mrow1 = Mb + (size_t)(row0 + 8) * S_;

    const int NT = S_ / ATK;   // 32 tiles
    for (int t = 0; t < NT; t++) {
        const int k0 = t * ATK;
        // issue next tile's loads into the other buffer
        if (t + 1 < NT) {
            const uint32_t nb = sb + AOFF_BUF + ((t + 1) & 1) * BUF_BYTES;
#pragma unroll
            for (int i = 0; i < 2; i++) {
                const int rr = krr + i * 32;
                const size_t g = (size_t)(k0 + ATK + rr) * D_ + kcc * 8;
                const uint32_t s = nb + rr * ALD + kcc * 16;
                CPASYNC16(s + BKH, &Khb[g]);
                CPASYNC16(s + BKL, &Klb[g]);
                CPASYNC16(s + BVH, &Vhb[g]);
                CPASYNC16(s + BVL, &Vlb[g]);
            }
            CPCOMMIT();
            CPWAIT1();
        } else {
            CPWAIT0();
        }
        __syncthreads();

        const uint32_t cb = sb + AOFF_BUF + (t & 1) * BUF_BYTES;
        const uint32_t boffK = cb + loffK;
        const uint32_t voffV = cb + loffV;

        // ---- S = Q K^T (split compensated) ----
        float Sf[8][4];
#pragma unroll
        for (int j = 0; j < 8; j++)
#pragma unroll
            for (int tt = 0; tt < 4; tt++) Sf[j][tt] = 0.0f;

#pragma unroll
        for (int kc = 0; kc < 4; kc++) {
            const uint32_t kb = (uint32_t)(kc * 32);
            uint32_t ah[4], al[4];
            ldsm4(ah[0], ah[1], ah[2], ah[3], aoffQ + AOFF_QH + kb);
            ldsm4(al[0], al[1], al[2], al[3], aoffQ + AOFF_QL + kb);
#pragma unroll
            for (int jp = 0; jp < 4; jp++) {
                uint32_t kh[4], kl[4];
                ldsm4(kh[0], kh[1], kh[2], kh[3],
                      boffK + BKH + (uint32_t)(jp * 16 * ALD) + kb);
                ldsm4(kl[0], kl[1], kl[2], kl[3],
                      boffK + BKL + (uint32_t)(jp * 16 * ALD) + kb);
                mma16816(Sf[jp * 2],     ah[0], ah[1], ah[2], ah[3], kh[0], kh[1]);
                mma16816(Sf[jp * 2],     ah[0], ah[1], ah[2], ah[3], kl[0], kl[1]);
                mma16816(Sf[jp * 2],     al[0], al[1], al[2], al[3], kh[0], kh[1]);
                mma16816(Sf[jp * 2 + 1], ah[0], ah[1], ah[2], ah[3], kh[2], kh[3]);
                mma16816(Sf[jp * 2 + 1], ah[0], ah[1], ah[2], ah[3], kl[2], kl[3]);
                mma16816(Sf[jp * 2 + 1], al[0], al[1], al[2], al[3], kh[2], kh[3]);
            }
        }

        // ---- scale + mask ----
#pragma unroll
        for (int j = 0; j < 8; j++) {
            int2 mv0 = *(const int2*)&mrow0[k0 + j * 8 + mcol];
            int2 mv1 = *(const int2*)&mrow1[k0 + j * 8 + mcol];
            Sf[j][0] = (mv0.x == 0) ? -1e9f : Sf[j][0] * 0.125f;
            Sf[j][1] = (mv0.y == 0) ? -1e9f : Sf[j][1] * 0.125f;
            Sf[j][2] = (mv1.x == 0) ? -1e9f : Sf[j][2] * 0.125f;
            Sf[j][3] = (mv1.y == 0) ? -1e9f : Sf[j][3] * 0.125f;
        }

        // ---- online softmax ----
        float corr[2];
#pragma unroll
        for (int rr = 0; rr < 2; rr++) {
            float mx = -1e30f;
#pragma unroll
            for (int j = 0; j < 8; j++)
                mx = fmaxf(mx, fmaxf(Sf[j][rr * 2], Sf[j][rr * 2 + 1]));
            mx = fmaxf(mx, __shfl_xor_sync(0xFFFFFFFF, mx, 1));
            mx = fmaxf(mx, __shfl_xor_sync(0xFFFFFFFF, mx, 2));
            float mnew = fmaxf(mstate[rr], mx);
            corr[rr] = __expf(mstate[rr] - mnew);
            float sum = 0.0f;
#pragma unroll
            for (int j = 0; j < 8; j++) {
                float p0 = __expf(Sf[j][rr * 2]     - mnew);
                float p1 = __expf(Sf[j][rr * 2 + 1] - mnew);
                Sf[j][rr * 2] = p0; Sf[j][rr * 2 + 1] = p1;
                sum += p0 + p1;
            }
            sum += __shfl_xor_sync(0xFFFFFFFF, sum, 1);
            sum += __shfl_xor_sync(0xFFFFFFFF, sum, 2);
            lstate[rr] = lstate[rr] * corr[rr] + sum;
            mstate[rr] = mnew;
        }

#pragma unroll
        for (int j = 0; j < 8; j++) {
            O[j][0] *= corr[0]; O[j][1] *= corr[0];
            O[j][2] *= corr[1]; O[j][3] *= corr[1];
        }

        // ---- pack P (hi/lo split) ----
        uint32_t aPh[4][4], aPl[4][4];
#pragma unroll
        for (int kc = 0; kc < 4; kc++) {
#pragma unroll
            for (int half = 0; half < 2; half++) {
                const int j = kc * 2 + half;
#pragma unroll
                for (int rr = 0; rr < 2; rr++) {
                    float p0 = Sf[j][rr * 2], p1 = Sf[j][rr * 2 + 1];
                    __nv_bfloat16 h0 = __float2bfloat16_rn(p0);
                    __nv_bfloat16 h1 = __float2bfloat16_rn(p1);
                    __nv_bfloat162 hp; hp.x = h0; hp.y = h1;
                    aPh[kc][half * 2 + rr] = *(uint32_t*)&hp;
                    aPl[kc][half * 2 + rr] =
                        packbf(p0 - __bfloat162float(h0), p1 - __bfloat162float(h1));
                }
            }
        }

        // ---- O += P V (split compensated) ----
#pragma unroll
        for (int kc = 0; kc < 4; kc++) {
#pragma unroll
            for (int jp = 0; jp < 4; jp++) {
                uint32_t vh[4], vl[4];
                ldsm4t(vh[0], vh[1], vh[2], vh[3],
                       voffV + BVH + (uint32_t)(kc * 16 * ALD) + (uint32_t)(jp * 32));
                ldsm4t(vl[0], vl[1], vl[2], vl[3],
                       voffV + BVL + (uint32_t)(kc * 16 * ALD) + (uint32_t)(jp * 32));
                mma16816(O[jp * 2],     aPh[kc][0], aPh[kc][1], aPh[kc][2], aPh[kc][3], vh[0], vh[1]);
                mma16816(O[jp * 2],     aPh[kc][0], aPh[kc][1], aPh[kc][2], aPh[kc][3], vl[0], vl[1]);
                mma16816(O[jp * 2],     aPl[kc][0], aPl[kc][1], aPl[kc][2], aPl[kc][3], vh[0], vh[1]);
                mma16816(O[jp * 2 + 1], aPh[kc][0], aPh[kc][1], aPh[kc][2], aPh[kc][3], vh[2], vh[3]);
                mma16816(O[jp * 2 + 1], aPh[kc][0], aPh[kc][1], aPh[kc][2], aPh[kc][3], vl[2], vl[3]);
                mma16816(O[jp * 2 + 1], aPl[kc][0], aPl[kc][1], aPl[kc][2], aPl[kc][3], vh[2], vh[3]);
            }
        }
        __syncthreads();   // done with buf (t&1) before it is refilled at t+2
    }

    // ---- finalize: write pre-split context ----
    const float inv0 = 1.0f / lstate[0];
    const float inv1 = 1.0f / lstate[1];
    __nv_bfloat16* Chb = Ch + base;
    __nv_bfloat16* Clb = Cl + base;
#pragma unroll
    for (int j = 0; j < 8; j++) {
        const int col = j * 8 + mcol;
        float v0 = O[j][0] * inv0, v1 = O[j][1] * inv0;
        float v2 = O[j][2] * inv1, v3 = O[j][3] * inv1;
        __nv_bfloat16 h0 = __float2bfloat16_rn(v0);
        __nv_bfloat16 h1 = __float2bfloat16_rn(v1);
        __nv_bfloat16 h2 = __float2bfloat16_rn(v2);
        __nv_bfloat16 h3 = __float2bfloat16_rn(v3);
        __nv_bfloat162 hp0; hp0.x = h0; hp0.y = h1;
        __nv_bfloat162 hp1; hp1.x = h2; hp1.y = h3;
        *(uint32_t*)&Chb[(size_t)row0 * D_ + col]       = *(uint32_t*)&hp0;
        *(uint32_t*)&Chb[(size_t)(row0 + 8) * D_ + col] = *(uint32_t*)&hp1;
        *(uint32_t*)&Clb[(size_t)row0 * D_ + col] =
            packbf(v0 - __bfloat162float(h0), v1 - __bfloat162float(h1));
        *(uint32_t*)&Clb[(size_t)(row0 + 8) * D_ + col] =
            packbf(v2 - __bfloat162float(h2), v3 - __bfloat162float(h3));
    }
}

// ---------------------------------------------------------------------------
// Launch
// ---------------------------------------------------------------------------
extern "C" void kernel_launch(void* const* d_in, const int* in_sizes, int n_in,
                              void* d_out, int out_size)
{
    (void)in_sizes; (void)n_in; (void)out_size;
    const float* q    = (const float*)d_in[0];
    const float* k    = (const float*)d_in[1];
    const float* v    = (const float*)d_in[2];
    const int*   mask = (const int*)d_in[3];
    const float* w_q  = (const float*)d_in[4];
    const float* b_q  = (const float*)d_in[5];
    const float* w_k  = (const float*)d_in[6];
    const float* b_k  = (const float*)d_in[7];
    const float* w_v  = (const float*)d_in[8];
    const float* b_v  = (const float*)d_in[9];
    const float* w_o  = (const float*)d_in[10];
    const float* b_o  = (const float*)d_in[11];
    float* out = (float*)d_out;

    __nv_bfloat16 *gQh, *gQl, *gKh, *gKl, *gVh, *gVl, *gCh, *gCl;
    cudaGetSymbolAddress((void**)&gQh, g_Qh);
    cudaGetSymbolAddress((void**)&gQl, g_Ql);
    cudaGetSymbolAddress((void**)&gKh, g_Kh);
    cudaGetSymbolAddress((void**)&gKl, g_Kl);
    cudaGetSymbolAddress((void**)&gVh, g_Vh);
    cudaGetSymbolAddress((void**)&gVl, g_Vl);
    cudaGetSymbolAddress((void**)&gCh, g_Ch);
    cudaGetSymbolAddress((void**)&gCl, g_Cl);

    cudaFuncSetAttribute(attn_mma_kernel,
                         cudaFuncAttributeMaxDynamicSharedMemorySize,
                         ATTN_SMEM_BYTES);

    dim3 gblk(256);

    // Q/K/V projections batched over z
    dim3 ggrid3(D_ / BN, M_ / BM, 3);
    gemm_mma_kernel<0><<<ggrid3, gblk>>>(
        q, k, v, nullptr, nullptr,
        w_q, w_k, w_v, b_q, b_k, b_v,
        nullptr,
        gQh, gKh, gVh, gQl, gKl, gVl);

    dim3 ablk(256);
    dim3 agrid(S_ / ATQ, B_ * H_);    // (16, 32)
    attn_mma_kernel<<<agrid, ablk, ATTN_SMEM_BYTES>>>(
        gQh, gQl, gKh, gKl, gVh, gVl, mask, gCh, gCl);

    // final projection (pre-split A)
    dim3 ggrid1(D_ / BN, M_ / BM, 1);
    gemm_mma_kernel<1><<<ggrid1, gblk>>>(
        nullptr, nullptr, nullptr, gCh, gCl,
        w_o, nullptr, nullptr, b_o, nullptr, nullptr,
        out,
        nullptr, nullptr, nullptr, nullptr, nullptr, nullptr);
}